// round 1
// baseline (speedup 1.0000x reference)
#include <cuda_runtime.h>
#include <math.h>

// ---------------- problem constants ----------------
#define SQ    4096          // sequence length
#define HSZ   1024          // hidden size
#define NHA   16            // attention heads
#define HD    64            // attn head dim
#define NHL   4             // lact heads
#define DINL  256           // lact head dim (= dh)
#define CHK   1024          // lact chunk size
#define NCH   4             // number of chunks
#define NBH   16            // NCH * NHL
#define CDSZ  (CHK*DINL)    // per chunk-head activation size

// ---------------- scratch (device globals, no allocations) ----------------
__device__ float g_xn[SQ*HSZ];
__device__ float g_qkv[SQ*3*HSZ];
__device__ float g_ao[SQ*HSZ];
__device__ float g_hidden[NBH*CDSZ];
__device__ float g_dpre[NBH*CDSZ];
__device__ float g_dg[NBH*CDSZ];
__device__ float g_u[NBH*CDSZ];
__device__ float g_w0n[NBH*DINL*DINL];
__device__ float g_w1n[NBH*DINL*DINL];
__device__ float g_w2n[NBH*DINL*DINL];

// ---------------- LayerNorm ----------------
__global__ __launch_bounds__(256) void ln_kernel(const float* __restrict__ x,
                                                 const float* __restrict__ w,
                                                 const float* __restrict__ b) {
    int row = blockIdx.x;
    const float* xr = x + row * HSZ;
    float* o = g_xn + row * HSZ;
    __shared__ float red[64];
    float s = 0.f, s2 = 0.f;
    for (int i = threadIdx.x; i < HSZ; i += 256) {
        float v = xr[i];
        s += v; s2 += v * v;
    }
    #pragma unroll
    for (int off = 16; off; off >>= 1) {
        s  += __shfl_down_sync(~0u, s,  off);
        s2 += __shfl_down_sync(~0u, s2, off);
    }
    int wid = threadIdx.x >> 5, lid = threadIdx.x & 31;
    if (lid == 0) { red[wid] = s; red[wid + 32] = s2; }
    __syncthreads();
    if (threadIdx.x == 0) {
        float ts = 0.f, ts2 = 0.f;
        for (int i = 0; i < 8; i++) { ts += red[i]; ts2 += red[i + 32]; }
        red[0] = ts / HSZ;
        red[1] = ts2 / HSZ;
    }
    __syncthreads();
    float mu  = red[0];
    float var = red[1] - mu * mu;
    float inv = rsqrtf(var + 1e-5f);
    for (int i = threadIdx.x; i < HSZ; i += 256) {
        o[i] = (xr[i] - mu) * inv * w[i] + b[i];
    }
}

// ---------------- generic GEMM: C[m,n] = sum_k A[m,k]*B[n,k] + bias[n] ----------------
// which==0: A=g_xn, C=g_qkv (qkv projection)
// which==1: A=g_ao, C=Cext (out projection, writes d_out)
__global__ __launch_bounds__(256) void gemm_bt_kernel(const float* __restrict__ B,
                                                      const float* __restrict__ bias,
                                                      float* __restrict__ Cext,
                                                      int which, int N, int K) {
    const float* A = (which == 0) ? g_xn : g_ao;
    float* C = (which == 0) ? g_qkv : Cext;
    __shared__ float As[64][16];
    __shared__ float Bs[16][65];
    int n0 = blockIdx.x * 64, m0 = blockIdx.y * 64;
    int tid = threadIdx.x, tx = tid & 15, ty = tid >> 4;
    float acc[4][4] = {};
    for (int k0 = 0; k0 < K; k0 += 16) {
        #pragma unroll
        for (int t = 0; t < 4; t++) {
            int idx = tid + t * 256;
            int r = idx >> 4, kk = idx & 15;
            As[r][kk] = A[(m0 + r) * K + k0 + kk];
            Bs[kk][r] = B[(n0 + r) * K + k0 + kk];
        }
        __syncthreads();
        #pragma unroll
        for (int kk = 0; kk < 16; kk++) {
            float a[4], b[4];
            #pragma unroll
            for (int i = 0; i < 4; i++) a[i] = As[ty * 4 + i][kk];
            #pragma unroll
            for (int j = 0; j < 4; j++) b[j] = Bs[kk][tx * 4 + j];
            #pragma unroll
            for (int i = 0; i < 4; i++)
                #pragma unroll
                for (int j = 0; j < 4; j++)
                    acc[i][j] += a[i] * b[j];
        }
        __syncthreads();
    }
    #pragma unroll
    for (int i = 0; i < 4; i++)
        #pragma unroll
        for (int j = 0; j < 4; j++) {
            int m = m0 + ty * 4 + i, n = n0 + tx * 4 + j;
            C[m * N + n] = acc[i][j] + bias[n];
        }
}

// ---------------- flash-style attention, fp32 ----------------
// grid (SQ/128, NHA), block 128. One q-row per thread; q,o in regs; online softmax.
__global__ __launch_bounds__(128) void attn_kernel() {
    __shared__ float ks[64][64];
    __shared__ float vs[64][64];
    int h = blockIdx.y;
    int row = blockIdx.x * 128 + threadIdx.x;
    const float* qp = g_qkv + row * (3 * HSZ) + h * HD;
    float q[64], o[64];
    #pragma unroll
    for (int d = 0; d < 64; d++) { q[d] = qp[d] * 0.125f; o[d] = 0.f; }
    float m = -1e30f, l = 0.f;
    for (int kt = 0; kt < SQ / 64; kt++) {
        __syncthreads();
        #pragma unroll
        for (int t = 0; t < 32; t++) {
            int idx = threadIdx.x + t * 128;
            int j = idx >> 6, d = idx & 63;
            int src = (kt * 64 + j) * (3 * HSZ) + h * HD + d;
            ks[j][d] = g_qkv[HSZ + src];
            vs[j][d] = g_qkv[2 * HSZ + src];
        }
        __syncthreads();
        #pragma unroll 1
        for (int j = 0; j < 64; j++) {
            float s = 0.f;
            #pragma unroll
            for (int d = 0; d < 64; d++) s += q[d] * ks[j][d];
            if (s > m) {
                float corr = __expf(m - s);
                l *= corr;
                #pragma unroll
                for (int d = 0; d < 64; d++) o[d] *= corr;
                m = s;
            }
            float p = __expf(s - m);
            l += p;
            #pragma unroll
            for (int d = 0; d < 64; d++) o[d] += p * vs[j][d];
        }
    }
    float invl = 1.f / l;
    float* op = g_ao + row * HSZ + h * HD;
    #pragma unroll
    for (int d = 0; d < 64; d++) op[d] = o[d] * invl;
}

// ---------------- LaCT forward: gate/g/dhid GEMMs fused + SwiGLU backward elementwise ----------------
// Per (chunk n, head h): X = xn[n*CHK .. , h*DINL ..]  [1024 x 256]
// gate = X@w0^T, gg = X@w2^T, xw1 = X@w1 ; outputs hidden, dpre, dg
__global__ __launch_bounds__(256) void lact_fwd_kernel(const float* __restrict__ w0,
                                                       const float* __restrict__ w1,
                                                       const float* __restrict__ w2) {
    __shared__ float Xs[64][16];
    __shared__ float Bg[16][65], Bx[16][65], Bh[16][65];
    int bh = blockIdx.z, n = bh >> 2, h = bh & 3;
    int e0 = blockIdx.x * 64, c0 = blockIdx.y * 64;
    const float* X   = g_xn + (n * CHK) * HSZ + h * DINL;
    const float* w0h = w0 + h * DINL * DINL;
    const float* w1h = w1 + h * DINL * DINL;
    const float* w2h = w2 + h * DINL * DINL;
    int tid = threadIdx.x, tx = tid & 15, ty = tid >> 4;
    float ag[4][4] = {}, ax[4][4] = {}, ah[4][4] = {};
    for (int k0 = 0; k0 < DINL; k0 += 16) {
        #pragma unroll
        for (int t = 0; t < 4; t++) {
            int idx = tid + t * 256;
            int r = idx >> 4, kk = idx & 15;
            Xs[r][kk] = X[(c0 + r) * HSZ + k0 + kk];
            Bg[kk][r] = w0h[(e0 + r) * DINL + k0 + kk];
            Bx[kk][r] = w2h[(e0 + r) * DINL + k0 + kk];
            int kk2 = idx >> 6, e2 = idx & 63;
            Bh[kk2][e2] = w1h[(k0 + kk2) * DINL + e0 + e2];
        }
        __syncthreads();
        #pragma unroll
        for (int kk = 0; kk < 16; kk++) {
            float xa[4], bg[4], bx[4], bh_[4];
            #pragma unroll
            for (int i = 0; i < 4; i++) xa[i] = Xs[ty * 4 + i][kk];
            #pragma unroll
            for (int j = 0; j < 4; j++) {
                bg[j] = Bg[kk][tx * 4 + j];
                bx[j] = Bx[kk][tx * 4 + j];
                bh_[j] = Bh[kk][tx * 4 + j];
            }
            #pragma unroll
            for (int i = 0; i < 4; i++)
                #pragma unroll
                for (int j = 0; j < 4; j++) {
                    ag[i][j] += xa[i] * bg[j];
                    ax[i][j] += xa[i] * bx[j];
                    ah[i][j] += xa[i] * bh_[j];
                }
        }
        __syncthreads();
    }
    float* hid = g_hidden + bh * CDSZ;
    float* dpr = g_dpre   + bh * CDSZ;
    float* dgp = g_dg     + bh * CDSZ;
    #pragma unroll
    for (int i = 0; i < 4; i++)
        #pragma unroll
        for (int j = 0; j < 4; j++) {
            int c = c0 + ty * 4 + i, e = e0 + tx * 4 + j;
            float gate = ag[i][j], gg = ax[i][j];
            float sg = 1.f / (1.f + __expf(-gate));
            float hs = gate * sg;                        // silu(gate)
            float dhid = -ah[i][j];                      // dout @ w1, dout = -X
            float dh = dhid * gg;
            int idx = c * DINL + e;
            hid[idx] = hs * gg;                          // hidden
            dgp[idx] = dhid * hs;                        // dg
            dpr[idx] = dh * (sg + gate * sg * (1.f - sg)); // dpre
        }
}

// ---------------- LaCT weight grads + SGD step ----------------
// C[i,j] = sum_c P[c,i] * Q[c,j];  w_out = w_base + sign * C
// mode 0: w0n = w0 - dpre^T X ; mode 1: w2n = w2 - dg^T X ; mode 2: w1n = w1 + X^T hidden
__global__ __launch_bounds__(256) void lact_dw_kernel(const float* __restrict__ w0,
                                                      const float* __restrict__ w1,
                                                      const float* __restrict__ w2) {
    __shared__ float Ps[16][65], Qs[16][65];
    int z = blockIdx.z;
    int mode = z % 3, bh = z / 3;
    int n = bh >> 2, h = bh & 3;
    int i0 = blockIdx.y * 64, j0 = blockIdx.x * 64;
    const float* Xp = g_xn + (n * CHK) * HSZ + h * DINL;
    const float *P, *Q, *wb;
    float* wo;
    int ldP, ldQ;
    float sign;
    if (mode == 0)      { P = g_dpre + bh * CDSZ; ldP = DINL; Q = Xp; ldQ = HSZ;
                          wb = w0 + h * DINL * DINL; wo = g_w0n + bh * DINL * DINL; sign = -1.f; }
    else if (mode == 1) { P = g_dg + bh * CDSZ; ldP = DINL; Q = Xp; ldQ = HSZ;
                          wb = w2 + h * DINL * DINL; wo = g_w2n + bh * DINL * DINL; sign = -1.f; }
    else                { P = Xp; ldP = HSZ; Q = g_hidden + bh * CDSZ; ldQ = DINL;
                          wb = w1 + h * DINL * DINL; wo = g_w1n + bh * DINL * DINL; sign = 1.f; }
    int tid = threadIdx.x, tx = tid & 15, ty = tid >> 4;
    float acc[4][4] = {};
    for (int k0 = 0; k0 < CHK; k0 += 16) {
        #pragma unroll
        for (int t = 0; t < 4; t++) {
            int idx = tid + t * 256;
            int kk = idx >> 6, ii = idx & 63;
            Ps[kk][ii] = P[(k0 + kk) * ldP + i0 + ii];
            Qs[kk][ii] = Q[(k0 + kk) * ldQ + j0 + ii];
        }
        __syncthreads();
        #pragma unroll
        for (int kk = 0; kk < 16; kk++) {
            float a[4], b[4];
            #pragma unroll
            for (int i = 0; i < 4; i++) a[i] = Ps[kk][ty * 4 + i];
            #pragma unroll
            for (int j = 0; j < 4; j++) b[j] = Qs[kk][tx * 4 + j];
            #pragma unroll
            for (int i = 0; i < 4; i++)
                #pragma unroll
                for (int j = 0; j < 4; j++)
                    acc[i][j] += a[i] * b[j];
        }
        __syncthreads();
    }
    #pragma unroll
    for (int i = 0; i < 4; i++)
        #pragma unroll
        for (int j = 0; j < 4; j++) {
            int ii = i0 + ty * 4 + i, jj = j0 + tx * 4 + j;
            wo[ii * DINL + jj] = wb[ii * DINL + jj] + sign * acc[i][j];
        }
}

// ---------------- LaCT apply part 1: gq = X@w0n^T, gq2 = X@w2n^T, u = silu(gq)*gq2 ----------------
__global__ __launch_bounds__(256) void lact_apply1_kernel() {
    __shared__ float Xs[64][16];
    __shared__ float B0s[16][65], B2s[16][65];
    int bh = blockIdx.z, n = bh >> 2, h = bh & 3;
    int e0 = blockIdx.x * 64, c0 = blockIdx.y * 64;
    const float* X   = g_xn + (n * CHK) * HSZ + h * DINL;
    const float* wa  = g_w0n + bh * DINL * DINL;
    const float* wc  = g_w2n + bh * DINL * DINL;
    int tid = threadIdx.x, tx = tid & 15, ty = tid >> 4;
    float a0[4][4] = {}, a2[4][4] = {};
    for (int k0 = 0; k0 < DINL; k0 += 16) {
        #pragma unroll
        for (int t = 0; t < 4; t++) {
            int idx = tid + t * 256;
            int r = idx >> 4, kk = idx & 15;
            Xs[r][kk]  = X[(c0 + r) * HSZ + k0 + kk];
            B0s[kk][r] = wa[(e0 + r) * DINL + k0 + kk];
            B2s[kk][r] = wc[(e0 + r) * DINL + k0 + kk];
        }
        __syncthreads();
        #pragma unroll
        for (int kk = 0; kk < 16; kk++) {
            float xa[4], b0[4], b2[4];
            #pragma unroll
            for (int i = 0; i < 4; i++) xa[i] = Xs[ty * 4 + i][kk];
            #pragma unroll
            for (int j = 0; j < 4; j++) { b0[j] = B0s[kk][tx * 4 + j]; b2[j] = B2s[kk][tx * 4 + j]; }
            #pragma unroll
            for (int i = 0; i < 4; i++)
                #pragma unroll
                for (int j = 0; j < 4; j++) {
                    a0[i][j] += xa[i] * b0[j];
                    a2[i][j] += xa[i] * b2[j];
                }
        }
        __syncthreads();
    }
    float* up = g_u + bh * CDSZ;
    #pragma unroll
    for (int i = 0; i < 4; i++)
        #pragma unroll
        for (int j = 0; j < 4; j++) {
            int c = c0 + ty * 4 + i, e = e0 + tx * 4 + j;
            float gq = a0[i][j];
            float sg = 1.f / (1.f + __expf(-gq));
            up[c * DINL + e] = gq * sg * a2[i][j];
        }
}

// ---------------- LaCT apply part 2: oq = u @ w1n^T, scatter-add into output ----------------
__global__ __launch_bounds__(256) void lact_apply2_kernel(float* __restrict__ out) {
    __shared__ float Us[64][16];
    __shared__ float Bs[16][65];
    int bh = blockIdx.z, n = bh >> 2, h = bh & 3;
    int d0 = blockIdx.x * 64, c0 = blockIdx.y * 64;
    const float* U   = g_u + bh * CDSZ;
    const float* w1n = g_w1n + bh * DINL * DINL;
    int tid = threadIdx.x, tx = tid & 15, ty = tid >> 4;
    float acc[4][4] = {};
    for (int k0 = 0; k0 < DINL; k0 += 16) {
        #pragma unroll
        for (int t = 0; t < 4; t++) {
            int idx = tid + t * 256;
            int r = idx >> 4, kk = idx & 15;
            Us[r][kk] = U[(c0 + r) * DINL + k0 + kk];
            Bs[kk][r] = w1n[(d0 + r) * DINL + k0 + kk];
        }
        __syncthreads();
        #pragma unroll
        for (int kk = 0; kk < 16; kk++) {
            float a[4], b[4];
            #pragma unroll
            for (int i = 0; i < 4; i++) a[i] = Us[ty * 4 + i][kk];
            #pragma unroll
            for (int j = 0; j < 4; j++) b[j] = Bs[kk][tx * 4 + j];
            #pragma unroll
            for (int i = 0; i < 4; i++)
                #pragma unroll
                for (int j = 0; j < 4; j++)
                    acc[i][j] += a[i] * b[j];
        }
        __syncthreads();
    }
    #pragma unroll
    for (int i = 0; i < 4; i++)
        #pragma unroll
        for (int j = 0; j < 4; j++) {
            int c = c0 + ty * 4 + i, d = d0 + tx * 4 + j;
            out[(n * CHK + c) * HSZ + h * DINL + d] += acc[i][j];
        }
}

// ---------------- launch ----------------
extern "C" void kernel_launch(void* const* d_in, const int* in_sizes, int n_in,
                              void* d_out, int out_size) {
    const float* x   = (const float*)d_in[0];
    const float* lnw = (const float*)d_in[1];
    const float* lnb = (const float*)d_in[2];
    const float* ipw = (const float*)d_in[3];
    const float* ipb = (const float*)d_in[4];
    const float* opw = (const float*)d_in[5];
    const float* opb = (const float*)d_in[6];
    const float* w0  = (const float*)d_in[7];
    const float* w1  = (const float*)d_in[8];
    const float* w2  = (const float*)d_in[9];
    float* out = (float*)d_out;

    ln_kernel<<<SQ, 256>>>(x, lnw, lnb);
    // qkv = xn @ in_proj_w^T + b
    gemm_bt_kernel<<<dim3(3 * HSZ / 64, SQ / 64), 256>>>(ipw, ipb, nullptr, 0, 3 * HSZ, HSZ);
    // attention
    attn_kernel<<<dim3(SQ / 128, NHA), 128>>>();
    // attn_out = ao @ out_proj_w^T + b  -> writes d_out
    gemm_bt_kernel<<<dim3(HSZ / 64, SQ / 64), 256>>>(opw, opb, out, 1, HSZ, HSZ);
    // lact: forward + swiglu backward elementwise
    lact_fwd_kernel<<<dim3(DINL / 64, CHK / 64, NBH), 256>>>(w0, w1, w2);
    // lact: weight grads + sgd step
    lact_dw_kernel<<<dim3(DINL / 64, DINL / 64, NBH * 3), 256>>>(w0, w1, w2);
    // lact: apply updated weights to queries
    lact_apply1_kernel<<<dim3(DINL / 64, CHK / 64, NBH), 256>>>();
    lact_apply2_kernel<<<dim3(DINL / 64, CHK / 64, NBH), 256>>>(out);
}

// round 2
// speedup vs baseline: 1.0040x; 1.0040x over previous
#include <cuda_runtime.h>
#include <math.h>

// ---------------- problem constants ----------------
#define SQ    4096          // sequence length
#define HSZ   1024          // hidden size
#define NHA   16            // attention heads
#define HD    64            // attn head dim
#define NHL   4             // lact heads
#define DINL  256           // lact head dim (= dh)
#define CHK   1024          // lact chunk size
#define NCH   4             // number of chunks
#define NBH   16            // NCH * NHL
#define CDSZ  (CHK*DINL)    // per chunk-head activation size

// ---------------- scratch (device globals, no allocations) ----------------
__device__ float g_xn[SQ*HSZ];
__device__ float g_qkv[SQ*3*HSZ];
__device__ float g_ao[SQ*HSZ];
__device__ float g_hidden[NBH*CDSZ];
__device__ float g_dpre[NBH*CDSZ];
__device__ float g_dg[NBH*CDSZ];
__device__ float g_u[NBH*CDSZ];
__device__ float g_w0n[NBH*DINL*DINL];
__device__ float g_w1n[NBH*DINL*DINL];
__device__ float g_w2n[NBH*DINL*DINL];

// ---------------- LayerNorm ----------------
__global__ __launch_bounds__(256) void ln_kernel(const float* __restrict__ x,
                                                 const float* __restrict__ w,
                                                 const float* __restrict__ b) {
    int row = blockIdx.x;
    const float* xr = x + row * HSZ;
    float* o = g_xn + row * HSZ;
    __shared__ float red[64];
    float s = 0.f, s2 = 0.f;
    for (int i = threadIdx.x; i < HSZ; i += 256) {
        float v = xr[i];
        s += v; s2 += v * v;
    }
    #pragma unroll
    for (int off = 16; off; off >>= 1) {
        s  += __shfl_down_sync(~0u, s,  off);
        s2 += __shfl_down_sync(~0u, s2, off);
    }
    int wid = threadIdx.x >> 5, lid = threadIdx.x & 31;
    if (lid == 0) { red[wid] = s; red[wid + 32] = s2; }
    __syncthreads();
    if (threadIdx.x == 0) {
        float ts = 0.f, ts2 = 0.f;
        for (int i = 0; i < 8; i++) { ts += red[i]; ts2 += red[i + 32]; }
        red[0] = ts / HSZ;
        red[1] = ts2 / HSZ;
    }
    __syncthreads();
    float mu  = red[0];
    float var = red[1] - mu * mu;
    float inv = rsqrtf(var + 1e-5f);
    for (int i = threadIdx.x; i < HSZ; i += 256) {
        o[i] = (xr[i] - mu) * inv * w[i] + b[i];
    }
}

// ---------------- generic GEMM: C[m,n] = sum_k A[m,k]*B[n,k] + bias[n] ----------------
// which==0: A=g_xn, C=g_qkv (qkv projection)
// which==1: A=g_ao, C=Cext (out projection, writes d_out)
__global__ __launch_bounds__(256) void gemm_bt_kernel(const float* __restrict__ B,
                                                      const float* __restrict__ bias,
                                                      float* __restrict__ Cext,
                                                      int which, int N, int K) {
    const float* A = (which == 0) ? g_xn : g_ao;
    float* C = (which == 0) ? g_qkv : Cext;
    __shared__ float As[64][16];
    __shared__ float Bs[16][65];
    int n0 = blockIdx.x * 64, m0 = blockIdx.y * 64;
    int tid = threadIdx.x, tx = tid & 15, ty = tid >> 4;
    float acc[4][4] = {};
    for (int k0 = 0; k0 < K; k0 += 16) {
        #pragma unroll
        for (int t = 0; t < 4; t++) {
            int idx = tid + t * 256;
            int r = idx >> 4, kk = idx & 15;
            As[r][kk] = A[(m0 + r) * K + k0 + kk];
            Bs[kk][r] = B[(n0 + r) * K + k0 + kk];
        }
        __syncthreads();
        #pragma unroll
        for (int kk = 0; kk < 16; kk++) {
            float a[4], b[4];
            #pragma unroll
            for (int i = 0; i < 4; i++) a[i] = As[ty * 4 + i][kk];
            #pragma unroll
            for (int j = 0; j < 4; j++) b[j] = Bs[kk][tx * 4 + j];
            #pragma unroll
            for (int i = 0; i < 4; i++)
                #pragma unroll
                for (int j = 0; j < 4; j++)
                    acc[i][j] += a[i] * b[j];
        }
        __syncthreads();
    }
    #pragma unroll
    for (int i = 0; i < 4; i++)
        #pragma unroll
        for (int j = 0; j < 4; j++) {
            int m = m0 + ty * 4 + i, n = n0 + tx * 4 + j;
            C[m * N + n] = acc[i][j] + bias[n];
        }
}

// ---------------- flash-style attention, fp32 ----------------
// grid (SQ/128, NHA), block 128. One q-row per thread; q,o in regs; online softmax.
__global__ __launch_bounds__(128) void attn_kernel() {
    __shared__ float ks[64][64];
    __shared__ float vs[64][64];
    int h = blockIdx.y;
    int row = blockIdx.x * 128 + threadIdx.x;
    const float* qp = g_qkv + row * (3 * HSZ) + h * HD;
    float q[64], o[64];
    #pragma unroll
    for (int d = 0; d < 64; d++) { q[d] = qp[d] * 0.125f; o[d] = 0.f; }
    float m = -1e30f, l = 0.f;
    for (int kt = 0; kt < SQ / 64; kt++) {
        __syncthreads();
        #pragma unroll
        for (int t = 0; t < 32; t++) {
            int idx = threadIdx.x + t * 128;
            int j = idx >> 6, d = idx & 63;
            int src = (kt * 64 + j) * (3 * HSZ) + h * HD + d;
            ks[j][d] = g_qkv[HSZ + src];
            vs[j][d] = g_qkv[2 * HSZ + src];
        }
        __syncthreads();
        #pragma unroll 1
        for (int j = 0; j < 64; j++) {
            float s = 0.f;
            #pragma unroll
            for (int d = 0; d < 64; d++) s += q[d] * ks[j][d];
            if (s > m) {
                float corr = __expf(m - s);
                l *= corr;
                #pragma unroll
                for (int d = 0; d < 64; d++) o[d] *= corr;
                m = s;
            }
            float p = __expf(s - m);
            l += p;
            #pragma unroll
            for (int d = 0; d < 64; d++) o[d] += p * vs[j][d];
        }
    }
    float invl = 1.f / l;
    float* op = g_ao + row * HSZ + h * HD;
    #pragma unroll
    for (int d = 0; d < 64; d++) op[d] = o[d] * invl;
}

// ---------------- LaCT forward: gate/g/dhid GEMMs fused + SwiGLU backward elementwise ----------------
// Per (chunk n, head h): X = xn[n*CHK .. , h*DINL ..]  [1024 x 256]
// gate = X@w0^T, gg = X@w2^T, xw1 = X@w1 ; outputs hidden, dpre, dg
__global__ __launch_bounds__(256) void lact_fwd_kernel(const float* __restrict__ w0,
                                                       const float* __restrict__ w1,
                                                       const float* __restrict__ w2) {
    __shared__ float Xs[64][16];
    __shared__ float Bg[16][65], Bx[16][65], Bh[16][65];
    int bh = blockIdx.z, n = bh >> 2, h = bh & 3;
    int e0 = blockIdx.x * 64, c0 = blockIdx.y * 64;
    const float* X   = g_xn + (n * CHK) * HSZ + h * DINL;
    const float* w0h = w0 + h * DINL * DINL;
    const float* w1h = w1 + h * DINL * DINL;
    const float* w2h = w2 + h * DINL * DINL;
    int tid = threadIdx.x, tx = tid & 15, ty = tid >> 4;
    float ag[4][4] = {}, ax[4][4] = {}, ah[4][4] = {};
    for (int k0 = 0; k0 < DINL; k0 += 16) {
        #pragma unroll
        for (int t = 0; t < 4; t++) {
            int idx = tid + t * 256;
            int r = idx >> 4, kk = idx & 15;
            Xs[r][kk] = X[(c0 + r) * HSZ + k0 + kk];
            Bg[kk][r] = w0h[(e0 + r) * DINL + k0 + kk];
            Bx[kk][r] = w2h[(e0 + r) * DINL + k0 + kk];
            int kk2 = idx >> 6, e2 = idx & 63;
            Bh[kk2][e2] = w1h[(k0 + kk2) * DINL + e0 + e2];
        }
        __syncthreads();
        #pragma unroll
        for (int kk = 0; kk < 16; kk++) {
            float xa[4], bg[4], bx[4], bh_[4];
            #pragma unroll
            for (int i = 0; i < 4; i++) xa[i] = Xs[ty * 4 + i][kk];
            #pragma unroll
            for (int j = 0; j < 4; j++) {
                bg[j] = Bg[kk][tx * 4 + j];
                bx[j] = Bx[kk][tx * 4 + j];
                bh_[j] = Bh[kk][tx * 4 + j];
            }
            #pragma unroll
            for (int i = 0; i < 4; i++)
                #pragma unroll
                for (int j = 0; j < 4; j++) {
                    ag[i][j] += xa[i] * bg[j];
                    ax[i][j] += xa[i] * bx[j];
                    ah[i][j] += xa[i] * bh_[j];
                }
        }
        __syncthreads();
    }
    float* hid = g_hidden + bh * CDSZ;
    float* dpr = g_dpre   + bh * CDSZ;
    float* dgp = g_dg     + bh * CDSZ;
    #pragma unroll
    for (int i = 0; i < 4; i++)
        #pragma unroll
        for (int j = 0; j < 4; j++) {
            int c = c0 + ty * 4 + i, e = e0 + tx * 4 + j;
            float gate = ag[i][j], gg = ax[i][j];
            float sg = 1.f / (1.f + __expf(-gate));
            float hs = gate * sg;                        // silu(gate)
            float dhid = -ah[i][j];                      // dout @ w1, dout = -X
            float dh = dhid * gg;
            int idx = c * DINL + e;
            hid[idx] = hs * gg;                          // hidden
            dgp[idx] = dhid * hs;                        // dg
            dpr[idx] = dh * (sg + gate * sg * (1.f - sg)); // dpre
        }
}

// ---------------- LaCT weight grads + SGD step ----------------
// C[i,j] = sum_c P[c,i] * Q[c,j];  w_out = w_base + sign * C
// mode 0: w0n = w0 - dpre^T X ; mode 1: w2n = w2 - dg^T X ; mode 2: w1n = w1 + X^T hidden
__global__ __launch_bounds__(256) void lact_dw_kernel(const float* __restrict__ w0,
                                                      const float* __restrict__ w1,
                                                      const float* __restrict__ w2) {
    __shared__ float Ps[16][65], Qs[16][65];
    int z = blockIdx.z;
    int mode = z % 3, bh = z / 3;
    int n = bh >> 2, h = bh & 3;
    int i0 = blockIdx.y * 64, j0 = blockIdx.x * 64;
    const float* Xp = g_xn + (n * CHK) * HSZ + h * DINL;
    const float *P, *Q, *wb;
    float* wo;
    int ldP, ldQ;
    float sign;
    if (mode == 0)      { P = g_dpre + bh * CDSZ; ldP = DINL; Q = Xp; ldQ = HSZ;
                          wb = w0 + h * DINL * DINL; wo = g_w0n + bh * DINL * DINL; sign = -1.f; }
    else if (mode == 1) { P = g_dg + bh * CDSZ; ldP = DINL; Q = Xp; ldQ = HSZ;
                          wb = w2 + h * DINL * DINL; wo = g_w2n + bh * DINL * DINL; sign = -1.f; }
    else                { P = Xp; ldP = HSZ; Q = g_hidden + bh * CDSZ; ldQ = DINL;
                          wb = w1 + h * DINL * DINL; wo = g_w1n + bh * DINL * DINL; sign = 1.f; }
    int tid = threadIdx.x, tx = tid & 15, ty = tid >> 4;
    float acc[4][4] = {};
    for (int k0 = 0; k0 < CHK; k0 += 16) {
        #pragma unroll
        for (int t = 0; t < 4; t++) {
            int idx = tid + t * 256;
            int kk = idx >> 6, ii = idx & 63;
            Ps[kk][ii] = P[(k0 + kk) * ldP + i0 + ii];
            Qs[kk][ii] = Q[(k0 + kk) * ldQ + j0 + ii];
        }
        __syncthreads();
        #pragma unroll
        for (int kk = 0; kk < 16; kk++) {
            float a[4], b[4];
            #pragma unroll
            for (int i = 0; i < 4; i++) a[i] = Ps[kk][ty * 4 + i];
            #pragma unroll
            for (int j = 0; j < 4; j++) b[j] = Qs[kk][tx * 4 + j];
            #pragma unroll
            for (int i = 0; i < 4; i++)
                #pragma unroll
                for (int j = 0; j < 4; j++)
                    acc[i][j] += a[i] * b[j];
        }
        __syncthreads();
    }
    #pragma unroll
    for (int i = 0; i < 4; i++)
        #pragma unroll
        for (int j = 0; j < 4; j++) {
            int ii = i0 + ty * 4 + i, jj = j0 + tx * 4 + j;
            wo[ii * DINL + jj] = wb[ii * DINL + jj] + sign * acc[i][j];
        }
}

// ---------------- LaCT apply part 1: gq = X@w0n^T, gq2 = X@w2n^T, u = silu(gq)*gq2 ----------------
__global__ __launch_bounds__(256) void lact_apply1_kernel() {
    __shared__ float Xs[64][16];
    __shared__ float B0s[16][65], B2s[16][65];
    int bh = blockIdx.z, n = bh >> 2, h = bh & 3;
    int e0 = blockIdx.x * 64, c0 = blockIdx.y * 64;
    const float* X   = g_xn + (n * CHK) * HSZ + h * DINL;
    const float* wa  = g_w0n + bh * DINL * DINL;
    const float* wc  = g_w2n + bh * DINL * DINL;
    int tid = threadIdx.x, tx = tid & 15, ty = tid >> 4;
    float a0[4][4] = {}, a2[4][4] = {};
    for (int k0 = 0; k0 < DINL; k0 += 16) {
        #pragma unroll
        for (int t = 0; t < 4; t++) {
            int idx = tid + t * 256;
            int r = idx >> 4, kk = idx & 15;
            Xs[r][kk]  = X[(c0 + r) * HSZ + k0 + kk];
            B0s[kk][r] = wa[(e0 + r) * DINL + k0 + kk];
            B2s[kk][r] = wc[(e0 + r) * DINL + k0 + kk];
        }
        __syncthreads();
        #pragma unroll
        for (int kk = 0; kk < 16; kk++) {
            float xa[4], b0[4], b2[4];
            #pragma unroll
            for (int i = 0; i < 4; i++) xa[i] = Xs[ty * 4 + i][kk];
            #pragma unroll
            for (int j = 0; j < 4; j++) { b0[j] = B0s[kk][tx * 4 + j]; b2[j] = B2s[kk][tx * 4 + j]; }
            #pragma unroll
            for (int i = 0; i < 4; i++)
                #pragma unroll
                for (int j = 0; j < 4; j++) {
                    a0[i][j] += xa[i] * b0[j];
                    a2[i][j] += xa[i] * b2[j];
                }
        }
        __syncthreads();
    }
    float* up = g_u + bh * CDSZ;
    #pragma unroll
    for (int i = 0; i < 4; i++)
        #pragma unroll
        for (int j = 0; j < 4; j++) {
            int c = c0 + ty * 4 + i, e = e0 + tx * 4 + j;
            float gq = a0[i][j];
            float sg = 1.f / (1.f + __expf(-gq));
            up[c * DINL + e] = gq * sg * a2[i][j];
        }
}

// ---------------- LaCT apply part 2: oq = u @ w1n^T, scatter-add into output ----------------
__global__ __launch_bounds__(256) void lact_apply2_kernel(float* __restrict__ out) {
    __shared__ float Us[64][16];
    __shared__ float Bs[16][65];
    int bh = blockIdx.z, n = bh >> 2, h = bh & 3;
    int d0 = blockIdx.x * 64, c0 = blockIdx.y * 64;
    const float* U   = g_u + bh * CDSZ;
    const float* w1n = g_w1n + bh * DINL * DINL;
    int tid = threadIdx.x, tx = tid & 15, ty = tid >> 4;
    float acc[4][4] = {};
    for (int k0 = 0; k0 < DINL; k0 += 16) {
        #pragma unroll
        for (int t = 0; t < 4; t++) {
            int idx = tid + t * 256;
            int r = idx >> 4, kk = idx & 15;
            Us[r][kk] = U[(c0 + r) * DINL + k0 + kk];
            Bs[kk][r] = w1n[(d0 + r) * DINL + k0 + kk];
        }
        __syncthreads();
        #pragma unroll
        for (int kk = 0; kk < 16; kk++) {
            float a[4], b[4];
            #pragma unroll
            for (int i = 0; i < 4; i++) a[i] = Us[ty * 4 + i][kk];
            #pragma unroll
            for (int j = 0; j < 4; j++) b[j] = Bs[kk][tx * 4 + j];
            #pragma unroll
            for (int i = 0; i < 4; i++)
                #pragma unroll
                for (int j = 0; j < 4; j++)
                    acc[i][j] += a[i] * b[j];
        }
        __syncthreads();
    }
    #pragma unroll
    for (int i = 0; i < 4; i++)
        #pragma unroll
        for (int j = 0; j < 4; j++) {
            int c = c0 + ty * 4 + i, d = d0 + tx * 4 + j;
            out[(n * CHK + c) * HSZ + h * DINL + d] += acc[i][j];
        }
}

// ---------------- launch ----------------
extern "C" void kernel_launch(void* const* d_in, const int* in_sizes, int n_in,
                              void* d_out, int out_size) {
    const float* x   = (const float*)d_in[0];
    const float* lnw = (const float*)d_in[1];
    const float* lnb = (const float*)d_in[2];
    const float* ipw = (const float*)d_in[3];
    const float* ipb = (const float*)d_in[4];
    const float* opw = (const float*)d_in[5];
    const float* opb = (const float*)d_in[6];
    const float* w0  = (const float*)d_in[7];
    const float* w1  = (const float*)d_in[8];
    const float* w2  = (const float*)d_in[9];
    float* out = (float*)d_out;

    ln_kernel<<<SQ, 256>>>(x, lnw, lnb);
    // qkv = xn @ in_proj_w^T + b
    gemm_bt_kernel<<<dim3(3 * HSZ / 64, SQ / 64), 256>>>(ipw, ipb, nullptr, 0, 3 * HSZ, HSZ);
    // attention
    attn_kernel<<<dim3(SQ / 128, NHA), 128>>>();
    // attn_out = ao @ out_proj_w^T + b  -> writes d_out
    gemm_bt_kernel<<<dim3(HSZ / 64, SQ / 64), 256>>>(opw, opb, out, 1, HSZ, HSZ);
    // lact: forward + swiglu backward elementwise
    lact_fwd_kernel<<<dim3(DINL / 64, CHK / 64, NBH), 256>>>(w0, w1, w2);
    // lact: weight grads + sgd step
    lact_dw_kernel<<<dim3(DINL / 64, DINL / 64, NBH * 3), 256>>>(w0, w1, w2);
    // lact: apply updated weights to queries
    lact_apply1_kernel<<<dim3(DINL / 64, CHK / 64, NBH), 256>>>();
    lact_apply2_kernel<<<dim3(DINL / 64, CHK / 64, NBH), 256>>>(out);
}

// round 3
// speedup vs baseline: 3.2959x; 3.2829x over previous
#include <cuda_runtime.h>
#include <cuda_bf16.h>
#include <math.h>

// ---------------- problem constants ----------------
#define SQ    4096          // sequence length
#define HSZ   1024          // hidden size
#define NHA   16            // attention heads
#define HD    64            // attn head dim
#define NHL   4             // lact heads
#define DINL  256           // lact head dim (= dh)
#define CHK   1024          // lact chunk size
#define NCH   4             // number of chunks
#define NBH   16            // NCH * NHL
#define CDSZ  (CHK*DINL)    // per chunk-head activation size

// ---------------- scratch (device globals, no allocations) ----------------
__device__ float g_xn[SQ*HSZ];
__device__ float g_qkv[SQ*3*HSZ];
__device__ float g_ao[SQ*HSZ];
__device__ float g_hidden[NBH*CDSZ];
__device__ float g_dpre[NBH*CDSZ];
__device__ float g_dg[NBH*CDSZ];
__device__ float g_u[NBH*CDSZ];
__device__ float g_w0n[NBH*DINL*DINL];
__device__ float g_w1n[NBH*DINL*DINL];
__device__ float g_w2n[NBH*DINL*DINL];

// ---------------- mma helpers ----------------
__device__ __forceinline__ void mma16816(float c[4],
                                         unsigned a0, unsigned a1, unsigned a2, unsigned a3,
                                         unsigned b0, unsigned b1) {
    asm volatile(
        "mma.sync.aligned.m16n8k16.row.col.f32.bf16.bf16.f32 "
        "{%0,%1,%2,%3}, {%4,%5,%6,%7}, {%8,%9}, {%0,%1,%2,%3};\n"
        : "+f"(c[0]), "+f"(c[1]), "+f"(c[2]), "+f"(c[3])
        : "r"(a0), "r"(a1), "r"(a2), "r"(a3), "r"(b0), "r"(b1));
}

// split two fp32 values into packed bf16 hi pair and lo (residual) pair
__device__ __forceinline__ void split_pack(float x, float y, unsigned &h, unsigned &l) {
    __nv_bfloat16 hx = __float2bfloat16_rn(x), hy = __float2bfloat16_rn(y);
    __nv_bfloat162 H; H.x = hx; H.y = hy;
    h = *reinterpret_cast<unsigned*>(&H);
    __nv_bfloat162 L;
    L.x = __float2bfloat16_rn(x - __bfloat162float(hx));
    L.y = __float2bfloat16_rn(y - __bfloat162float(hy));
    l = *reinterpret_cast<unsigned*>(&L);
}

// ---------------- LayerNorm ----------------
__global__ __launch_bounds__(256) void ln_kernel(const float* __restrict__ x,
                                                 const float* __restrict__ w,
                                                 const float* __restrict__ b) {
    int row = blockIdx.x;
    const float* xr = x + row * HSZ;
    float* o = g_xn + row * HSZ;
    __shared__ float red[64];
    float s = 0.f, s2 = 0.f;
    for (int i = threadIdx.x; i < HSZ; i += 256) {
        float v = xr[i];
        s += v; s2 += v * v;
    }
    #pragma unroll
    for (int off = 16; off; off >>= 1) {
        s  += __shfl_down_sync(~0u, s,  off);
        s2 += __shfl_down_sync(~0u, s2, off);
    }
    int wid = threadIdx.x >> 5, lid = threadIdx.x & 31;
    if (lid == 0) { red[wid] = s; red[wid + 32] = s2; }
    __syncthreads();
    if (threadIdx.x == 0) {
        float ts = 0.f, ts2 = 0.f;
        for (int i = 0; i < 8; i++) { ts += red[i]; ts2 += red[i + 32]; }
        red[0] = ts / HSZ;
        red[1] = ts2 / HSZ;
    }
    __syncthreads();
    float mu  = red[0];
    float var = red[1] - mu * mu;
    float inv = rsqrtf(var + 1e-5f);
    for (int i = threadIdx.x; i < HSZ; i += 256) {
        o[i] = (xr[i] - mu) * inv * w[i] + b[i];
    }
}

// ---------------- tensor-core GEMM: C[m,n] = sum_k A[m,k]*B[n,k] + bias[n] ----------------
// split bf16 (hi+lo), fp32 accumulate. BM=128, BN=64, BK=32, 256 threads (8 warps, 4x2).
// which==0: A=g_xn, C=g_qkv ; which==1: A=g_ao, C=Cext
__global__ __launch_bounds__(256) void gemm_mma_kernel(const float* __restrict__ Bw,
                                                       const float* __restrict__ bias,
                                                       float* __restrict__ Cext,
                                                       int which, int N, int K) {
    const float* A = (which == 0) ? g_xn : g_ao;
    float* C = (which == 0) ? g_qkv : Cext;
    __shared__ __nv_bfloat16 Ah[128][40], Al[128][40], Bh[64][40], Bl[64][40];
    int n0 = blockIdx.x * 64, m0 = blockIdx.y * 128;
    int tid = threadIdx.x;
    int wid = tid >> 5, lane = tid & 31;
    int g = lane >> 2, c = lane & 3;
    int wm = (wid & 3) * 32, wn = (wid >> 2) * 32;
    float acc[2][4][4];
    #pragma unroll
    for (int i = 0; i < 2; i++)
        #pragma unroll
        for (int j = 0; j < 4; j++)
            #pragma unroll
            for (int q = 0; q < 4; q++) acc[i][j][q] = 0.f;

    for (int k0 = 0; k0 < K; k0 += 32) {
        __syncthreads();
        #pragma unroll
        for (int p = 0; p < 4; p++) {
            int idx = tid + p * 256;
            int r = idx >> 3, cc = (idx & 7) * 4;
            float4 v = *(const float4*)(A + (m0 + r) * K + k0 + cc);
            unsigned hh, ll;
            split_pack(v.x, v.y, hh, ll);
            *(unsigned*)&Ah[r][cc] = hh; *(unsigned*)&Al[r][cc] = ll;
            split_pack(v.z, v.w, hh, ll);
            *(unsigned*)&Ah[r][cc + 2] = hh; *(unsigned*)&Al[r][cc + 2] = ll;
        }
        #pragma unroll
        for (int p = 0; p < 2; p++) {
            int idx = tid + p * 256;
            int r = idx >> 3, cc = (idx & 7) * 4;
            float4 v = *(const float4*)(Bw + (n0 + r) * K + k0 + cc);
            unsigned hh, ll;
            split_pack(v.x, v.y, hh, ll);
            *(unsigned*)&Bh[r][cc] = hh; *(unsigned*)&Bl[r][cc] = ll;
            split_pack(v.z, v.w, hh, ll);
            *(unsigned*)&Bh[r][cc + 2] = hh; *(unsigned*)&Bl[r][cc + 2] = ll;
        }
        __syncthreads();
        #pragma unroll
        for (int ks = 0; ks < 32; ks += 16) {
            unsigned ah[2][4], al[2][4];
            #pragma unroll
            for (int im = 0; im < 2; im++) {
                int mr = wm + im * 16;
                ah[im][0] = *(unsigned*)&Ah[mr + g][ks + 2 * c];
                ah[im][1] = *(unsigned*)&Ah[mr + g + 8][ks + 2 * c];
                ah[im][2] = *(unsigned*)&Ah[mr + g][ks + 2 * c + 8];
                ah[im][3] = *(unsigned*)&Ah[mr + g + 8][ks + 2 * c + 8];
                al[im][0] = *(unsigned*)&Al[mr + g][ks + 2 * c];
                al[im][1] = *(unsigned*)&Al[mr + g + 8][ks + 2 * c];
                al[im][2] = *(unsigned*)&Al[mr + g][ks + 2 * c + 8];
                al[im][3] = *(unsigned*)&Al[mr + g + 8][ks + 2 * c + 8];
            }
            #pragma unroll
            for (int jn = 0; jn < 4; jn++) {
                int nr = wn + jn * 8 + g;
                unsigned b0 = *(unsigned*)&Bh[nr][ks + 2 * c];
                unsigned b1 = *(unsigned*)&Bh[nr][ks + 2 * c + 8];
                unsigned l0 = *(unsigned*)&Bl[nr][ks + 2 * c];
                unsigned l1 = *(unsigned*)&Bl[nr][ks + 2 * c + 8];
                #pragma unroll
                for (int im = 0; im < 2; im++) {
                    mma16816(acc[im][jn], ah[im][0], ah[im][1], ah[im][2], ah[im][3], b0, b1);
                    mma16816(acc[im][jn], ah[im][0], ah[im][1], ah[im][2], ah[im][3], l0, l1);
                    mma16816(acc[im][jn], al[im][0], al[im][1], al[im][2], al[im][3], b0, b1);
                }
            }
        }
    }
    #pragma unroll
    for (int im = 0; im < 2; im++)
        #pragma unroll
        for (int jn = 0; jn < 4; jn++) {
            int row = m0 + wm + im * 16 + g;
            int col = n0 + wn + jn * 8 + 2 * c;
            float b0v = bias[col], b1v = bias[col + 1];
            C[row * N + col]           = acc[im][jn][0] + b0v;
            C[row * N + col + 1]       = acc[im][jn][1] + b1v;
            C[(row + 8) * N + col]     = acc[im][jn][2] + b0v;
            C[(row + 8) * N + col + 1] = acc[im][jn][3] + b1v;
        }
}

// ---------------- tensor-core flash attention ----------------
// grid (SQ/64, NHA), block 128 (4 warps x 16 q-rows). split-bf16 QK^T and PV.
__global__ __launch_bounds__(128) void attn_mma_kernel() {
    __shared__ __nv_bfloat16 Ksh[64][72], Ksl[64][72];   // [key j][d]
    __shared__ __nv_bfloat16 Vsh[64][72], Vsl[64][72];   // transposed: [d][key j]
    int h = blockIdx.y;
    int qt = blockIdx.x;
    int tid = threadIdx.x;
    int w = tid >> 5, lane = tid & 31;
    int g = lane >> 2, c = lane & 3;
    int qr0 = qt * 64 + w * 16;

    // Q fragments (persistent, scaled by hd^-0.5)
    unsigned qh[4][4], ql[4][4];
    #pragma unroll
    for (int kt = 0; kt < 4; kt++) {
        #pragma unroll
        for (int half = 0; half < 2; half++) {
            int d0 = kt * 16 + 2 * c + half * 8;
            const float* p0 = g_qkv + (qr0 + g) * (3 * HSZ) + h * HD + d0;
            const float* p1 = g_qkv + (qr0 + g + 8) * (3 * HSZ) + h * HD + d0;
            split_pack(p0[0] * 0.125f, p0[1] * 0.125f, qh[kt][half * 2], ql[kt][half * 2]);
            split_pack(p1[0] * 0.125f, p1[1] * 0.125f, qh[kt][half * 2 + 1], ql[kt][half * 2 + 1]);
        }
    }

    float o[8][4];
    #pragma unroll
    for (int i = 0; i < 8; i++)
        #pragma unroll
        for (int j = 0; j < 4; j++) o[i][j] = 0.f;
    float m0 = -1e30f, m1 = -1e30f, l0 = 0.f, l1 = 0.f;

    for (int kb = 0; kb < SQ / 64; kb++) {
        __syncthreads();
        #pragma unroll
        for (int p = 0; p < 8; p++) {
            int idx = tid + p * 128;
            int r = idx >> 4;
            int cc = (idx & 15) * 4;
            const float4 kv4 = *(const float4*)(g_qkv + HSZ + (kb * 64 + r) * (3 * HSZ) + h * HD + cc);
            unsigned hh, ll;
            split_pack(kv4.x, kv4.y, hh, ll);
            *(unsigned*)&Ksh[r][cc] = hh; *(unsigned*)&Ksl[r][cc] = ll;
            split_pack(kv4.z, kv4.w, hh, ll);
            *(unsigned*)&Ksh[r][cc + 2] = hh; *(unsigned*)&Ksl[r][cc + 2] = ll;
            const float4 vv4 = *(const float4*)(g_qkv + 2 * HSZ + (kb * 64 + r) * (3 * HSZ) + h * HD + cc);
            float vals[4] = {vv4.x, vv4.y, vv4.z, vv4.w};
            #pragma unroll
            for (int q2 = 0; q2 < 4; q2++) {
                __nv_bfloat16 hv = __float2bfloat16_rn(vals[q2]);
                Vsh[cc + q2][r] = hv;
                Vsl[cc + q2][r] = __float2bfloat16_rn(vals[q2] - __bfloat162float(hv));
            }
        }
        __syncthreads();

        // S = Q K^T (split: hi*hi + hi*lo + lo*hi)
        float s[8][4];
        #pragma unroll
        for (int i = 0; i < 8; i++)
            #pragma unroll
            for (int j = 0; j < 4; j++) s[i][j] = 0.f;
        #pragma unroll
        for (int kt = 0; kt < 4; kt++) {
            #pragma unroll
            for (int jn = 0; jn < 8; jn++) {
                int n = jn * 8 + g;
                unsigned b0 = *(unsigned*)&Ksh[n][kt * 16 + 2 * c];
                unsigned b1 = *(unsigned*)&Ksh[n][kt * 16 + 2 * c + 8];
                unsigned e0 = *(unsigned*)&Ksl[n][kt * 16 + 2 * c];
                unsigned e1 = *(unsigned*)&Ksl[n][kt * 16 + 2 * c + 8];
                mma16816(s[jn], qh[kt][0], qh[kt][1], qh[kt][2], qh[kt][3], b0, b1);
                mma16816(s[jn], qh[kt][0], qh[kt][1], qh[kt][2], qh[kt][3], e0, e1);
                mma16816(s[jn], ql[kt][0], ql[kt][1], ql[kt][2], ql[kt][3], b0, b1);
            }
        }

        // online softmax (rows g and g+8; quad = lanes sharing t>>2)
        float mx0 = s[0][0], mx1 = s[0][2];
        #pragma unroll
        for (int jn = 0; jn < 8; jn++) {
            mx0 = fmaxf(mx0, fmaxf(s[jn][0], s[jn][1]));
            mx1 = fmaxf(mx1, fmaxf(s[jn][2], s[jn][3]));
        }
        mx0 = fmaxf(mx0, __shfl_xor_sync(~0u, mx0, 1));
        mx0 = fmaxf(mx0, __shfl_xor_sync(~0u, mx0, 2));
        mx1 = fmaxf(mx1, __shfl_xor_sync(~0u, mx1, 1));
        mx1 = fmaxf(mx1, __shfl_xor_sync(~0u, mx1, 2));
        float nm0 = fmaxf(m0, mx0), nm1 = fmaxf(m1, mx1);
        float cr0 = __expf(m0 - nm0), cr1 = __expf(m1 - nm1);
        l0 *= cr0; l1 *= cr1;
        #pragma unroll
        for (int dn = 0; dn < 8; dn++) {
            o[dn][0] *= cr0; o[dn][1] *= cr0;
            o[dn][2] *= cr1; o[dn][3] *= cr1;
        }
        float ps0 = 0.f, ps1 = 0.f;
        #pragma unroll
        for (int jn = 0; jn < 8; jn++) {
            s[jn][0] = __expf(s[jn][0] - nm0); s[jn][1] = __expf(s[jn][1] - nm0);
            s[jn][2] = __expf(s[jn][2] - nm1); s[jn][3] = __expf(s[jn][3] - nm1);
            ps0 += s[jn][0] + s[jn][1]; ps1 += s[jn][2] + s[jn][3];
        }
        l0 += ps0; l1 += ps1;
        m0 = nm0; m1 = nm1;

        // O += P V  (P from S C-frags -> A-frags, split)
        #pragma unroll
        for (int kt = 0; kt < 4; kt++) {
            unsigned ph[4], pl[4];
            split_pack(s[2 * kt][0],     s[2 * kt][1],     ph[0], pl[0]);
            split_pack(s[2 * kt][2],     s[2 * kt][3],     ph[1], pl[1]);
            split_pack(s[2 * kt + 1][0], s[2 * kt + 1][1], ph[2], pl[2]);
            split_pack(s[2 * kt + 1][2], s[2 * kt + 1][3], ph[3], pl[3]);
            #pragma unroll
            for (int dn = 0; dn < 8; dn++) {
                int n = dn * 8 + g;
                unsigned b0 = *(unsigned*)&Vsh[n][kt * 16 + 2 * c];
                unsigned b1 = *(unsigned*)&Vsh[n][kt * 16 + 2 * c + 8];
                unsigned e0 = *(unsigned*)&Vsl[n][kt * 16 + 2 * c];
                unsigned e1 = *(unsigned*)&Vsl[n][kt * 16 + 2 * c + 8];
                mma16816(o[dn], ph[0], ph[1], ph[2], ph[3], b0, b1);
                mma16816(o[dn], ph[0], ph[1], ph[2], ph[3], e0, e1);
                mma16816(o[dn], pl[0], pl[1], pl[2], pl[3], b0, b1);
            }
        }
    }

    l0 += __shfl_xor_sync(~0u, l0, 1); l0 += __shfl_xor_sync(~0u, l0, 2);
    l1 += __shfl_xor_sync(~0u, l1, 1); l1 += __shfl_xor_sync(~0u, l1, 2);
    float i0 = 1.f / l0, i1 = 1.f / l1;
    #pragma unroll
    for (int dn = 0; dn < 8; dn++) {
        int col = h * HD + dn * 8 + 2 * c;
        g_ao[(qr0 + g) * HSZ + col]         = o[dn][0] * i0;
        g_ao[(qr0 + g) * HSZ + col + 1]     = o[dn][1] * i0;
        g_ao[(qr0 + g + 8) * HSZ + col]     = o[dn][2] * i1;
        g_ao[(qr0 + g + 8) * HSZ + col + 1] = o[dn][3] * i1;
    }
}

// ---------------- LaCT forward: gate/g/dhid GEMMs fused + SwiGLU backward elementwise ----------------
__global__ __launch_bounds__(256) void lact_fwd_kernel(const float* __restrict__ w0,
                                                       const float* __restrict__ w1,
                                                       const float* __restrict__ w2) {
    __shared__ float Xs[64][16];
    __shared__ float Bg[16][65], Bx[16][65], Bh2[16][65];
    int bh = blockIdx.z, n = bh >> 2, h = bh & 3;
    int e0 = blockIdx.x * 64, c0 = blockIdx.y * 64;
    const float* X   = g_xn + (n * CHK) * HSZ + h * DINL;
    const float* w0h = w0 + h * DINL * DINL;
    const float* w1h = w1 + h * DINL * DINL;
    const float* w2h = w2 + h * DINL * DINL;
    int tid = threadIdx.x, tx = tid & 15, ty = tid >> 4;
    float ag[4][4] = {}, ax[4][4] = {}, ah[4][4] = {};
    for (int k0 = 0; k0 < DINL; k0 += 16) {
        #pragma unroll
        for (int t = 0; t < 4; t++) {
            int idx = tid + t * 256;
            int r = idx >> 4, kk = idx & 15;
            Xs[r][kk] = X[(c0 + r) * HSZ + k0 + kk];
            Bg[kk][r] = w0h[(e0 + r) * DINL + k0 + kk];
            Bx[kk][r] = w2h[(e0 + r) * DINL + k0 + kk];
            int kk2 = idx >> 6, e2 = idx & 63;
            Bh2[kk2][e2] = w1h[(k0 + kk2) * DINL + e0 + e2];
        }
        __syncthreads();
        #pragma unroll
        for (int kk = 0; kk < 16; kk++) {
            float xa[4], bg[4], bx[4], bhv[4];
            #pragma unroll
            for (int i = 0; i < 4; i++) xa[i] = Xs[ty * 4 + i][kk];
            #pragma unroll
            for (int j = 0; j < 4; j++) {
                bg[j] = Bg[kk][tx * 4 + j];
                bx[j] = Bx[kk][tx * 4 + j];
                bhv[j] = Bh2[kk][tx * 4 + j];
            }
            #pragma unroll
            for (int i = 0; i < 4; i++)
                #pragma unroll
                for (int j = 0; j < 4; j++) {
                    ag[i][j] += xa[i] * bg[j];
                    ax[i][j] += xa[i] * bx[j];
                    ah[i][j] += xa[i] * bhv[j];
                }
        }
        __syncthreads();
    }
    float* hid = g_hidden + bh * CDSZ;
    float* dpr = g_dpre   + bh * CDSZ;
    float* dgp = g_dg     + bh * CDSZ;
    #pragma unroll
    for (int i = 0; i < 4; i++)
        #pragma unroll
        for (int j = 0; j < 4; j++) {
            int cc = c0 + ty * 4 + i, e = e0 + tx * 4 + j;
            float gate = ag[i][j], gg = ax[i][j];
            float sg = 1.f / (1.f + __expf(-gate));
            float hs = gate * sg;
            float dhid = -ah[i][j];
            float dh = dhid * gg;
            int idx = cc * DINL + e;
            hid[idx] = hs * gg;
            dgp[idx] = dhid * hs;
            dpr[idx] = dh * (sg + gate * sg * (1.f - sg));
        }
}

// ---------------- LaCT weight grads + SGD step ----------------
__global__ __launch_bounds__(256) void lact_dw_kernel(const float* __restrict__ w0,
                                                      const float* __restrict__ w1,
                                                      const float* __restrict__ w2) {
    __shared__ float Ps[16][65], Qs[16][65];
    int z = blockIdx.z;
    int mode = z % 3, bh = z / 3;
    int n = bh >> 2, h = bh & 3;
    int i0 = blockIdx.y * 64, j0 = blockIdx.x * 64;
    const float* Xp = g_xn + (n * CHK) * HSZ + h * DINL;
    const float *P, *Q, *wb;
    float* wo;
    int ldP, ldQ;
    float sign;
    if (mode == 0)      { P = g_dpre + bh * CDSZ; ldP = DINL; Q = Xp; ldQ = HSZ;
                          wb = w0 + h * DINL * DINL; wo = g_w0n + bh * DINL * DINL; sign = -1.f; }
    else if (mode == 1) { P = g_dg + bh * CDSZ; ldP = DINL; Q = Xp; ldQ = HSZ;
                          wb = w2 + h * DINL * DINL; wo = g_w2n + bh * DINL * DINL; sign = -1.f; }
    else                { P = Xp; ldP = HSZ; Q = g_hidden + bh * CDSZ; ldQ = DINL;
                          wb = w1 + h * DINL * DINL; wo = g_w1n + bh * DINL * DINL; sign = 1.f; }
    int tid = threadIdx.x, tx = tid & 15, ty = tid >> 4;
    float acc[4][4] = {};
    for (int k0 = 0; k0 < CHK; k0 += 16) {
        #pragma unroll
        for (int t = 0; t < 4; t++) {
            int idx = tid + t * 256;
            int kk = idx >> 6, ii = idx & 63;
            Ps[kk][ii] = P[(k0 + kk) * ldP + i0 + ii];
            Qs[kk][ii] = Q[(k0 + kk) * ldQ + j0 + ii];
        }
        __syncthreads();
        #pragma unroll
        for (int kk = 0; kk < 16; kk++) {
            float a[4], b[4];
            #pragma unroll
            for (int i = 0; i < 4; i++) a[i] = Ps[kk][ty * 4 + i];
            #pragma unroll
            for (int j = 0; j < 4; j++) b[j] = Qs[kk][tx * 4 + j];
            #pragma unroll
            for (int i = 0; i < 4; i++)
                #pragma unroll
                for (int j = 0; j < 4; j++)
                    acc[i][j] += a[i] * b[j];
        }
        __syncthreads();
    }
    #pragma unroll
    for (int i = 0; i < 4; i++)
        #pragma unroll
        for (int j = 0; j < 4; j++) {
            int ii = i0 + ty * 4 + i, jj = j0 + tx * 4 + j;
            wo[ii * DINL + jj] = wb[ii * DINL + jj] + sign * acc[i][j];
        }
}

// ---------------- LaCT apply part 1 ----------------
__global__ __launch_bounds__(256) void lact_apply1_kernel() {
    __shared__ float Xs[64][16];
    __shared__ float B0s[16][65], B2s[16][65];
    int bh = blockIdx.z, n = bh >> 2, h = bh & 3;
    int e0 = blockIdx.x * 64, c0 = blockIdx.y * 64;
    const float* X   = g_xn + (n * CHK) * HSZ + h * DINL;
    const float* wa  = g_w0n + bh * DINL * DINL;
    const float* wc  = g_w2n + bh * DINL * DINL;
    int tid = threadIdx.x, tx = tid & 15, ty = tid >> 4;
    float a0[4][4] = {}, a2[4][4] = {};
    for (int k0 = 0; k0 < DINL; k0 += 16) {
        #pragma unroll
        for (int t = 0; t < 4; t++) {
            int idx = tid + t * 256;
            int r = idx >> 4, kk = idx & 15;
            Xs[r][kk]  = X[(c0 + r) * HSZ + k0 + kk];
            B0s[kk][r] = wa[(e0 + r) * DINL + k0 + kk];
            B2s[kk][r] = wc[(e0 + r) * DINL + k0 + kk];
        }
        __syncthreads();
        #pragma unroll
        for (int kk = 0; kk < 16; kk++) {
            float xa[4], b0[4], b2[4];
            #pragma unroll
            for (int i = 0; i < 4; i++) xa[i] = Xs[ty * 4 + i][kk];
            #pragma unroll
            for (int j = 0; j < 4; j++) { b0[j] = B0s[kk][tx * 4 + j]; b2[j] = B2s[kk][tx * 4 + j]; }
            #pragma unroll
            for (int i = 0; i < 4; i++)
                #pragma unroll
                for (int j = 0; j < 4; j++) {
                    a0[i][j] += xa[i] * b0[j];
                    a2[i][j] += xa[i] * b2[j];
                }
        }
        __syncthreads();
    }
    float* up = g_u + bh * CDSZ;
    #pragma unroll
    for (int i = 0; i < 4; i++)
        #pragma unroll
        for (int j = 0; j < 4; j++) {
            int cc = c0 + ty * 4 + i, e = e0 + tx * 4 + j;
            float gq = a0[i][j];
            float sg = 1.f / (1.f + __expf(-gq));
            up[cc * DINL + e] = gq * sg * a2[i][j];
        }
}

// ---------------- LaCT apply part 2 ----------------
__global__ __launch_bounds__(256) void lact_apply2_kernel(float* __restrict__ out) {
    __shared__ float Us[64][16];
    __shared__ float Bs[16][65];
    int bh = blockIdx.z, n = bh >> 2, h = bh & 3;
    int d0 = blockIdx.x * 64, c0 = blockIdx.y * 64;
    const float* U   = g_u + bh * CDSZ;
    const float* w1n = g_w1n + bh * DINL * DINL;
    int tid = threadIdx.x, tx = tid & 15, ty = tid >> 4;
    float acc[4][4] = {};
    for (int k0 = 0; k0 < DINL; k0 += 16) {
        #pragma unroll
        for (int t = 0; t < 4; t++) {
            int idx = tid + t * 256;
            int r = idx >> 4, kk = idx & 15;
            Us[r][kk] = U[(c0 + r) * DINL + k0 + kk];
            Bs[kk][r] = w1n[(d0 + r) * DINL + k0 + kk];
        }
        __syncthreads();
        #pragma unroll
        for (int kk = 0; kk < 16; kk++) {
            float a[4], b[4];
            #pragma unroll
            for (int i = 0; i < 4; i++) a[i] = Us[ty * 4 + i][kk];
            #pragma unroll
            for (int j = 0; j < 4; j++) b[j] = Bs[kk][tx * 4 + j];
            #pragma unroll
            for (int i = 0; i < 4; i++)
                #pragma unroll
                for (int j = 0; j < 4; j++)
                    acc[i][j] += a[i] * b[j];
        }
        __syncthreads();
    }
    #pragma unroll
    for (int i = 0; i < 4; i++)
        #pragma unroll
        for (int j = 0; j < 4; j++) {
            int cc = c0 + ty * 4 + i, d = d0 + tx * 4 + j;
            out[(n * CHK + cc) * HSZ + h * DINL + d] += acc[i][j];
        }
}

// ---------------- launch ----------------
extern "C" void kernel_launch(void* const* d_in, const int* in_sizes, int n_in,
                              void* d_out, int out_size) {
    const float* x   = (const float*)d_in[0];
    const float* lnw = (const float*)d_in[1];
    const float* lnb = (const float*)d_in[2];
    const float* ipw = (const float*)d_in[3];
    const float* ipb = (const float*)d_in[4];
    const float* opw = (const float*)d_in[5];
    const float* opb = (const float*)d_in[6];
    const float* w0  = (const float*)d_in[7];
    const float* w1  = (const float*)d_in[8];
    const float* w2  = (const float*)d_in[9];
    float* out = (float*)d_out;

    ln_kernel<<<SQ, 256>>>(x, lnw, lnb);
    // qkv = xn @ in_proj_w^T + b   (tensor cores)
    gemm_mma_kernel<<<dim3(3 * HSZ / 64, SQ / 128), 256>>>(ipw, ipb, nullptr, 0, 3 * HSZ, HSZ);
    // attention (tensor cores)
    attn_mma_kernel<<<dim3(SQ / 64, NHA), 128>>>();
    // attn_out = ao @ out_proj_w^T + b  -> writes d_out
    gemm_mma_kernel<<<dim3(HSZ / 64, SQ / 128), 256>>>(opw, opb, out, 1, HSZ, HSZ);
    // lact branch (SIMT, small GEMMs)
    lact_fwd_kernel<<<dim3(DINL / 64, CHK / 64, NBH), 256>>>(w0, w1, w2);
    lact_dw_kernel<<<dim3(DINL / 64, DINL / 64, NBH * 3), 256>>>(w0, w1, w2);
    lact_apply1_kernel<<<dim3(DINL / 64, CHK / 64, NBH), 256>>>();
    lact_apply2_kernel<<<dim3(DINL / 64, CHK / 64, NBH), 256>>>(out);
}

// round 5
// speedup vs baseline: 4.5914x; 1.3930x over previous
#include <cuda_runtime.h>
#include <cuda_fp16.h>
#include <cuda_bf16.h>
#include <math.h>

// ---------------- problem constants ----------------
#define SQ    4096
#define HSZ   1024
#define NHA   16
#define HD    64
#define NHL   4
#define DINL  256
#define CHK   1024
#define NCH   4
#define NBH   16
#define CDSZ  (CHK*DINL)

// u scaling to keep fp16 in range in apply2 (exact power of two)
#define USCALE     2.44140625e-4f   // 2^-12
#define USCALE_INV 4096.0f

// ---------------- scratch ----------------
__device__ float g_xn[SQ*HSZ];
__device__ float g_qkv[SQ*3*HSZ];
__device__ float g_ao[SQ*HSZ];
__device__ float g_hidden[NBH*CDSZ];
__device__ float g_dpre[NBH*CDSZ];
__device__ float g_dg[NBH*CDSZ];
__device__ float g_u[NBH*CDSZ];
__device__ float g_w0n[NBH*DINL*DINL];
__device__ float g_w1n[NBH*DINL*DINL];
__device__ float g_w2n[NBH*DINL*DINL];
// precomputed fp16 split K [h][s][64 perm] and V^T [h][d][4096 perm]
__device__ __half g_kh[NHA*SQ*HD];
__device__ __half g_kl[NHA*SQ*HD];
__device__ __half g_vh[NHA*HD*SQ];
__device__ __half g_vl[NHA*HD*SQ];

// ---------------- mma helpers ----------------
__device__ __forceinline__ void mma_bf16(float c[4],
                                         unsigned a0, unsigned a1, unsigned a2, unsigned a3,
                                         unsigned b0, unsigned b1) {
    asm volatile(
        "mma.sync.aligned.m16n8k16.row.col.f32.bf16.bf16.f32 "
        "{%0,%1,%2,%3}, {%4,%5,%6,%7}, {%8,%9}, {%0,%1,%2,%3};\n"
        : "+f"(c[0]), "+f"(c[1]), "+f"(c[2]), "+f"(c[3])
        : "r"(a0), "r"(a1), "r"(a2), "r"(a3), "r"(b0), "r"(b1));
}
__device__ __forceinline__ void mma_f16(float c[4],
                                        unsigned a0, unsigned a1, unsigned a2, unsigned a3,
                                        unsigned b0, unsigned b1) {
    asm volatile(
        "mma.sync.aligned.m16n8k16.row.col.f32.f16.f16.f32 "
        "{%0,%1,%2,%3}, {%4,%5,%6,%7}, {%8,%9}, {%0,%1,%2,%3};\n"
        : "+f"(c[0]), "+f"(c[1]), "+f"(c[2]), "+f"(c[3])
        : "r"(a0), "r"(a1), "r"(a2), "r"(a3), "r"(b0), "r"(b1));
}

__device__ __forceinline__ void split_pack_bf(float x, float y, unsigned &h, unsigned &l) {
    __nv_bfloat16 hx = __float2bfloat16_rn(x), hy = __float2bfloat16_rn(y);
    __nv_bfloat162 H; H.x = hx; H.y = hy;
    h = *reinterpret_cast<unsigned*>(&H);
    __nv_bfloat162 L;
    L.x = __float2bfloat16_rn(x - __bfloat162float(hx));
    L.y = __float2bfloat16_rn(y - __bfloat162float(hy));
    l = *reinterpret_cast<unsigned*>(&L);
}
__device__ __forceinline__ void split_pack_h(float x, float y, unsigned &h, unsigned &l) {
    __half hx = __float2half_rn(x), hy = __float2half_rn(y);
    __half2 H = __halves2half2(hx, hy);
    h = *reinterpret_cast<unsigned*>(&H);
    __half2 L = __halves2half2(__float2half_rn(x - __half2float(hx)),
                               __float2half_rn(y - __half2float(hy)));
    l = *reinterpret_cast<unsigned*>(&L);
}
__device__ __forceinline__ void split_h(float x, __half &h, __half &l) {
    h = __float2half_rn(x);
    l = __float2half_rn(x - __half2float(h));
}

// ---------------- LayerNorm ----------------
__global__ __launch_bounds__(256) void ln_kernel(const float* __restrict__ x,
                                                 const float* __restrict__ w,
                                                 const float* __restrict__ b) {
    int row = blockIdx.x;
    const float* xr = x + row * HSZ;
    float* o = g_xn + row * HSZ;
    __shared__ float red[64];
    float s = 0.f, s2 = 0.f;
    for (int i = threadIdx.x; i < HSZ; i += 256) {
        float v = xr[i];
        s += v; s2 += v * v;
    }
    #pragma unroll
    for (int off = 16; off; off >>= 1) {
        s  += __shfl_down_sync(~0u, s,  off);
        s2 += __shfl_down_sync(~0u, s2, off);
    }
    int wid = threadIdx.x >> 5, lid = threadIdx.x & 31;
    if (lid == 0) { red[wid] = s; red[wid + 32] = s2; }
    __syncthreads();
    if (threadIdx.x == 0) {
        float ts = 0.f, ts2 = 0.f;
        for (int i = 0; i < 8; i++) { ts += red[i]; ts2 += red[i + 32]; }
        red[0] = ts / HSZ;
        red[1] = ts2 / HSZ;
    }
    __syncthreads();
    float mu  = red[0];
    float var = red[1] - mu * mu;
    float inv = rsqrtf(var + 1e-5f);
    for (int i = threadIdx.x; i < HSZ; i += 256) {
        o[i] = (xr[i] - mu) * inv * w[i] + b[i];
    }
}

// ---------------- big projections (split-bf16 mma, proven) ----------------
__global__ __launch_bounds__(256) void gemm_mma_kernel(const float* __restrict__ Bw,
                                                       const float* __restrict__ bias,
                                                       float* __restrict__ Cext,
                                                       int which, int N, int K) {
    const float* A = (which == 0) ? g_xn : g_ao;
    float* C = (which == 0) ? g_qkv : Cext;
    __shared__ __nv_bfloat16 Ah[128][40], Al[128][40], Bh[64][40], Bl[64][40];
    int n0 = blockIdx.x * 64, m0 = blockIdx.y * 128;
    int tid = threadIdx.x;
    int wid = tid >> 5, lane = tid & 31;
    int g = lane >> 2, c = lane & 3;
    int wm = (wid & 3) * 32, wn = (wid >> 2) * 32;
    float acc[2][4][4];
    #pragma unroll
    for (int i = 0; i < 2; i++)
        #pragma unroll
        for (int j = 0; j < 4; j++)
            #pragma unroll
            for (int q = 0; q < 4; q++) acc[i][j][q] = 0.f;

    for (int k0 = 0; k0 < K; k0 += 32) {
        __syncthreads();
        #pragma unroll
        for (int p = 0; p < 4; p++) {
            int idx = tid + p * 256;
            int r = idx >> 3, cc = (idx & 7) * 4;
            float4 v = *(const float4*)(A + (m0 + r) * K + k0 + cc);
            unsigned hh, ll;
            split_pack_bf(v.x, v.y, hh, ll);
            *(unsigned*)&Ah[r][cc] = hh; *(unsigned*)&Al[r][cc] = ll;
            split_pack_bf(v.z, v.w, hh, ll);
            *(unsigned*)&Ah[r][cc + 2] = hh; *(unsigned*)&Al[r][cc + 2] = ll;
        }
        #pragma unroll
        for (int p = 0; p < 2; p++) {
            int idx = tid + p * 256;
            int r = idx >> 3, cc = (idx & 7) * 4;
            float4 v = *(const float4*)(Bw + (n0 + r) * K + k0 + cc);
            unsigned hh, ll;
            split_pack_bf(v.x, v.y, hh, ll);
            *(unsigned*)&Bh[r][cc] = hh; *(unsigned*)&Bl[r][cc] = ll;
            split_pack_bf(v.z, v.w, hh, ll);
            *(unsigned*)&Bh[r][cc + 2] = hh; *(unsigned*)&Bl[r][cc + 2] = ll;
        }
        __syncthreads();
        #pragma unroll
        for (int ks = 0; ks < 32; ks += 16) {
            unsigned ah[2][4], al[2][4];
            #pragma unroll
            for (int im = 0; im < 2; im++) {
                int mr = wm + im * 16;
                ah[im][0] = *(unsigned*)&Ah[mr + g][ks + 2 * c];
                ah[im][1] = *(unsigned*)&Ah[mr + g + 8][ks + 2 * c];
                ah[im][2] = *(unsigned*)&Ah[mr + g][ks + 2 * c + 8];
                ah[im][3] = *(unsigned*)&Ah[mr + g + 8][ks + 2 * c + 8];
                al[im][0] = *(unsigned*)&Al[mr + g][ks + 2 * c];
                al[im][1] = *(unsigned*)&Al[mr + g + 8][ks + 2 * c];
                al[im][2] = *(unsigned*)&Al[mr + g][ks + 2 * c + 8];
                al[im][3] = *(unsigned*)&Al[mr + g + 8][ks + 2 * c + 8];
            }
            #pragma unroll
            for (int jn = 0; jn < 4; jn++) {
                int nr = wn + jn * 8 + g;
                unsigned b0 = *(unsigned*)&Bh[nr][ks + 2 * c];
                unsigned b1 = *(unsigned*)&Bh[nr][ks + 2 * c + 8];
                unsigned l0 = *(unsigned*)&Bl[nr][ks + 2 * c];
                unsigned l1 = *(unsigned*)&Bl[nr][ks + 2 * c + 8];
                #pragma unroll
                for (int im = 0; im < 2; im++) {
                    mma_bf16(acc[im][jn], ah[im][0], ah[im][1], ah[im][2], ah[im][3], b0, b1);
                    mma_bf16(acc[im][jn], ah[im][0], ah[im][1], ah[im][2], ah[im][3], l0, l1);
                    mma_bf16(acc[im][jn], al[im][0], al[im][1], al[im][2], al[im][3], b0, b1);
                }
            }
        }
    }
    #pragma unroll
    for (int im = 0; im < 2; im++)
        #pragma unroll
        for (int jn = 0; jn < 4; jn++) {
            int row = m0 + wm + im * 16 + g;
            int col = n0 + wn + jn * 8 + 2 * c;
            float b0v = bias[col], b1v = bias[col + 1];
            C[row * N + col]           = acc[im][jn][0] + b0v;
            C[row * N + col + 1]       = acc[im][jn][1] + b1v;
            C[(row + 8) * N + col]     = acc[im][jn][2] + b0v;
            C[(row + 8) * N + col + 1] = acc[im][jn][3] + b1v;
        }
}

// ---------------- K/V fp16-split precompute (mma-permuted k order) ----------------
__device__ __forceinline__ int permpos(int r) {  // r even
    int rr = r & 15;
    return (r & ~15) + ((rr & 7) >> 1) * 4 + ((rr >> 3) & 1) * 2;
}

__global__ __launch_bounds__(256) void cvt_k_kernel() {
    int h = blockIdx.y, s0 = blockIdx.x * 64;
    #pragma unroll
    for (int p = 0; p < 8; p++) {
        int idx = threadIdx.x + p * 256;           // 64 s x 32 d-pairs
        int s = idx >> 5, d = (idx & 31) * 2;
        const float* src = g_qkv + (s0 + s) * (3 * HSZ) + HSZ + h * 64 + d;
        __half hx, lx, hy, ly;
        split_h(src[0], hx, lx);
        split_h(src[1], hy, ly);
        int pos = permpos(d);
        long base = ((long)(h * SQ) + s0 + s) * 64 + pos;
        *(__half2*)(g_kh + base) = __halves2half2(hx, hy);
        *(__half2*)(g_kl + base) = __halves2half2(lx, ly);
    }
}

__global__ __launch_bounds__(256) void cvt_v_kernel() {
    __shared__ float ts[64][65];
    int h = blockIdx.y, s0 = blockIdx.x * 64;
    #pragma unroll
    for (int p = 0; p < 16; p++) {
        int idx = threadIdx.x + p * 256;           // 64 s x 64 d
        int s = idx >> 6, d = idx & 63;
        ts[s][d] = g_qkv[(s0 + s) * (3 * HSZ) + 2 * HSZ + h * 64 + d];
    }
    __syncthreads();
    #pragma unroll
    for (int p = 0; p < 8; p++) {
        int idx = threadIdx.x + p * 256;           // 64 d x 32 s-pairs
        int d = idx >> 5, sp = (idx & 31) * 2;
        __half hx, lx, hy, ly;
        split_h(ts[sp][d], hx, lx);
        split_h(ts[sp + 1][d], hy, ly);
        int pos = permpos(sp);
        long base = ((long)(h * 64) + d) * SQ + s0 + pos;
        *(__half2*)(g_vh + base) = __halves2half2(hx, hy);
        *(__half2*)(g_vl + base) = __halves2half2(lx, ly);
    }
}

// ---------------- tensor-core flash attention ----------------
#define KSTR 80
__global__ __launch_bounds__(256) void attn_mma_kernel() {
    __shared__ __half Kh[64][KSTR], Kl[64][KSTR], Vh[64][KSTR], Vl[64][KSTR];
    int h = blockIdx.y;
    int qt = blockIdx.x;
    int tid = threadIdx.x;
    int w = tid >> 5, lane = tid & 31;
    int g = lane >> 2, c = lane & 3;
    int qr = qt * 128 + w * 16;

    unsigned qh[4][4], ql[4][4];
    {
        const float* p0 = g_qkv + (qr + g) * (3 * HSZ) + h * HD;
        const float* p1 = g_qkv + (qr + g + 8) * (3 * HSZ) + h * HD;
        #pragma unroll
        for (int kt = 0; kt < 4; kt++) {
            int d0 = kt * 16 + 2 * c;
            split_pack_h(p0[d0] * 0.125f,     p0[d0 + 1] * 0.125f, qh[kt][0], ql[kt][0]);
            split_pack_h(p1[d0] * 0.125f,     p1[d0 + 1] * 0.125f, qh[kt][1], ql[kt][1]);
            split_pack_h(p0[d0 + 8] * 0.125f, p0[d0 + 9] * 0.125f, qh[kt][2], ql[kt][2]);
            split_pack_h(p1[d0 + 8] * 0.125f, p1[d0 + 9] * 0.125f, qh[kt][3], ql[kt][3]);
        }
    }

    float o[8][4];
    #pragma unroll
    for (int i = 0; i < 8; i++)
        #pragma unroll
        for (int j = 0; j < 4; j++) o[i][j] = 0.f;
    float m0 = -1e30f, m1 = -1e30f, l0 = 0.f, l1 = 0.f;

    for (int kb = 0; kb < SQ / 64; kb++) {
        __syncthreads();
        #pragma unroll
        for (int p = 0; p < 2; p++) {
            int r = (tid >> 3) + p * 32, seg = tid & 7;
            long kbase = ((long)(h * SQ) + kb * 64 + r) * 64 + seg * 8;
            *(uint4*)&Kh[r][seg * 8] = *(const uint4*)(g_kh + kbase);
            *(uint4*)&Kl[r][seg * 8] = *(const uint4*)(g_kl + kbase);
            long vbase = ((long)(h * 64) + r) * SQ + kb * 64 + seg * 8;
            *(uint4*)&Vh[r][seg * 8] = *(const uint4*)(g_vh + vbase);
            *(uint4*)&Vl[r][seg * 8] = *(const uint4*)(g_vl + vbase);
        }
        __syncthreads();

        float s[8][4];
        #pragma unroll
        for (int i = 0; i < 8; i++)
            #pragma unroll
            for (int j = 0; j < 4; j++) s[i][j] = 0.f;
        #pragma unroll
        for (int kt = 0; kt < 4; kt++) {
            #pragma unroll
            for (int jn = 0; jn < 8; jn++) {
                int n = jn * 8 + g;
                uint2 bh = *(const uint2*)&Kh[n][kt * 16 + 4 * c];
                uint2 bl = *(const uint2*)&Kl[n][kt * 16 + 4 * c];
                mma_f16(s[jn], qh[kt][0], qh[kt][1], qh[kt][2], qh[kt][3], bh.x, bh.y);
                mma_f16(s[jn], qh[kt][0], qh[kt][1], qh[kt][2], qh[kt][3], bl.x, bl.y);
                mma_f16(s[jn], ql[kt][0], ql[kt][1], ql[kt][2], ql[kt][3], bh.x, bh.y);
            }
        }

        float mx0 = s[0][0], mx1 = s[0][2];
        #pragma unroll
        for (int jn = 0; jn < 8; jn++) {
            mx0 = fmaxf(mx0, fmaxf(s[jn][0], s[jn][1]));
            mx1 = fmaxf(mx1, fmaxf(s[jn][2], s[jn][3]));
        }
        mx0 = fmaxf(mx0, __shfl_xor_sync(~0u, mx0, 1));
        mx0 = fmaxf(mx0, __shfl_xor_sync(~0u, mx0, 2));
        mx1 = fmaxf(mx1, __shfl_xor_sync(~0u, mx1, 1));
        mx1 = fmaxf(mx1, __shfl_xor_sync(~0u, mx1, 2));
        float nm0 = fmaxf(m0, mx0), nm1 = fmaxf(m1, mx1);
        float cr0 = __expf(m0 - nm0), cr1 = __expf(m1 - nm1);
        l0 *= cr0; l1 *= cr1;
        #pragma unroll
        for (int dn = 0; dn < 8; dn++) {
            o[dn][0] *= cr0; o[dn][1] *= cr0;
            o[dn][2] *= cr1; o[dn][3] *= cr1;
        }
        float ps0 = 0.f, ps1 = 0.f;
        #pragma unroll
        for (int jn = 0; jn < 8; jn++) {
            s[jn][0] = __expf(s[jn][0] - nm0); s[jn][1] = __expf(s[jn][1] - nm0);
            s[jn][2] = __expf(s[jn][2] - nm1); s[jn][3] = __expf(s[jn][3] - nm1);
            ps0 += s[jn][0] + s[jn][1]; ps1 += s[jn][2] + s[jn][3];
        }
        l0 += ps0; l1 += ps1;
        m0 = nm0; m1 = nm1;

        #pragma unroll
        for (int kt = 0; kt < 4; kt++) {
            unsigned ph[4];
            __half2 t;
            t = __float22half2_rn(make_float2(s[2 * kt][0],     s[2 * kt][1]));     ph[0] = *(unsigned*)&t;
            t = __float22half2_rn(make_float2(s[2 * kt][2],     s[2 * kt][3]));     ph[1] = *(unsigned*)&t;
            t = __float22half2_rn(make_float2(s[2 * kt + 1][0], s[2 * kt + 1][1])); ph[2] = *(unsigned*)&t;
            t = __float22half2_rn(make_float2(s[2 * kt + 1][2], s[2 * kt + 1][3])); ph[3] = *(unsigned*)&t;
            #pragma unroll
            for (int dn = 0; dn < 8; dn++) {
                int n = dn * 8 + g;
                uint2 vh = *(const uint2*)&Vh[n][kt * 16 + 4 * c];
                uint2 vl = *(const uint2*)&Vl[n][kt * 16 + 4 * c];
                mma_f16(o[dn], ph[0], ph[1], ph[2], ph[3], vh.x, vh.y);
                mma_f16(o[dn], ph[0], ph[1], ph[2], ph[3], vl.x, vl.y);
            }
        }
    }

    l0 += __shfl_xor_sync(~0u, l0, 1); l0 += __shfl_xor_sync(~0u, l0, 2);
    l1 += __shfl_xor_sync(~0u, l1, 1); l1 += __shfl_xor_sync(~0u, l1, 2);
    float i0 = 1.f / l0, i1 = 1.f / l1;
    #pragma unroll
    for (int dn = 0; dn < 8; dn++) {
        int col = h * HD + dn * 8 + 2 * c;
        g_ao[(qr + g) * HSZ + col]         = o[dn][0] * i0;
        g_ao[(qr + g) * HSZ + col + 1]     = o[dn][1] * i0;
        g_ao[(qr + g + 8) * HSZ + col]     = o[dn][2] * i1;
        g_ao[(qr + g + 8) * HSZ + col + 1] = o[dn][3] * i1;
    }
}

// ---------------- LaCT forward (mma): 3 GEMMs sharing A tile + SwiGLU bwd epilogue ----------------
#define LPAD 36
__global__ __launch_bounds__(256) void lact_fwd_mma(const float* __restrict__ w0,
                                                    const float* __restrict__ w1,
                                                    const float* __restrict__ w2) {
    __shared__ __half Ah[128][LPAD], Al[128][LPAD];
    __shared__ __half B0h[64][LPAD], B0l[64][LPAD], B1h[64][LPAD], B1l[64][LPAD],
                      B2h[64][LPAD], B2l[64][LPAD];
    int bh = blockIdx.z, n = bh >> 2, h = bh & 3;
    int e0 = blockIdx.x * 64, c0 = blockIdx.y * 128;
    const float* X    = g_xn + n * CHK * HSZ + h * DINL;
    const float* w0h_ = w0 + h * DINL * DINL;
    const float* w1h_ = w1 + h * DINL * DINL;
    const float* w2h_ = w2 + h * DINL * DINL;
    int tid = threadIdx.x, wid = tid >> 5, lane = tid & 31;
    int g = lane >> 2, c = lane & 3;
    int wm = (wid & 3) * 32, wn = (wid >> 2) * 32;
    float ag[2][4][4] = {}, ax[2][4][4] = {}, aw[2][4][4] = {};

    for (int k0 = 0; k0 < DINL; k0 += 32) {
        __syncthreads();
        #pragma unroll
        for (int p = 0; p < 8; p++) {
            int idx = tid + p * 256;
            int r = idx >> 4, cc = (idx & 15) * 2;
            const float* s = X + (c0 + r) * HSZ + k0 + cc;
            unsigned hh, ll;
            split_pack_h(s[0], s[1], hh, ll);
            *(unsigned*)&Ah[r][cc] = hh; *(unsigned*)&Al[r][cc] = ll;
        }
        #pragma unroll
        for (int p = 0; p < 4; p++) {
            int idx = tid + p * 256;
            int r = idx >> 4, cc = (idx & 15) * 2;
            unsigned hh, ll;
            const float* s0p = w0h_ + (e0 + r) * DINL + k0 + cc;
            split_pack_h(s0p[0], s0p[1], hh, ll);
            *(unsigned*)&B0h[r][cc] = hh; *(unsigned*)&B0l[r][cc] = ll;
            const float* s2p = w2h_ + (e0 + r) * DINL + k0 + cc;
            split_pack_h(s2p[0], s2p[1], hh, ll);
            *(unsigned*)&B1h[r][cc] = hh; *(unsigned*)&B1l[r][cc] = ll;
        }
        #pragma unroll
        for (int p = 0; p < 8; p++) {            // w1 transpose fill
            int idx = tid + p * 256;
            int kk = idx >> 6, ee = idx & 63;
            float v = w1h_[(k0 + kk) * DINL + e0 + ee];
            __half hv, lv; split_h(v, hv, lv);
            B2h[ee][kk] = hv; B2l[ee][kk] = lv;
        }
        __syncthreads();
        #pragma unroll
        for (int ks = 0; ks < 32; ks += 16) {
            unsigned ah[2][4], al[2][4];
            #pragma unroll
            for (int im = 0; im < 2; im++) {
                int mr = wm + im * 16;
                ah[im][0] = *(unsigned*)&Ah[mr + g][ks + 2 * c];
                ah[im][1] = *(unsigned*)&Ah[mr + g + 8][ks + 2 * c];
                ah[im][2] = *(unsigned*)&Ah[mr + g][ks + 2 * c + 8];
                ah[im][3] = *(unsigned*)&Ah[mr + g + 8][ks + 2 * c + 8];
                al[im][0] = *(unsigned*)&Al[mr + g][ks + 2 * c];
                al[im][1] = *(unsigned*)&Al[mr + g + 8][ks + 2 * c];
                al[im][2] = *(unsigned*)&Al[mr + g][ks + 2 * c + 8];
                al[im][3] = *(unsigned*)&Al[mr + g + 8][ks + 2 * c + 8];
            }
            #pragma unroll
            for (int jn = 0; jn < 4; jn++) {
                int nr = wn + jn * 8 + g;
                unsigned b0, b1, l0_, l1_;
                b0 = *(unsigned*)&B0h[nr][ks + 2 * c]; b1 = *(unsigned*)&B0h[nr][ks + 2 * c + 8];
                l0_ = *(unsigned*)&B0l[nr][ks + 2 * c]; l1_ = *(unsigned*)&B0l[nr][ks + 2 * c + 8];
                #pragma unroll
                for (int im = 0; im < 2; im++) {
                    mma_f16(ag[im][jn], ah[im][0], ah[im][1], ah[im][2], ah[im][3], b0, b1);
                    mma_f16(ag[im][jn], ah[im][0], ah[im][1], ah[im][2], ah[im][3], l0_, l1_);
                    mma_f16(ag[im][jn], al[im][0], al[im][1], al[im][2], al[im][3], b0, b1);
                }
                b0 = *(unsigned*)&B1h[nr][ks + 2 * c]; b1 = *(unsigned*)&B1h[nr][ks + 2 * c + 8];
                l0_ = *(unsigned*)&B1l[nr][ks + 2 * c]; l1_ = *(unsigned*)&B1l[nr][ks + 2 * c + 8];
                #pragma unroll
                for (int im = 0; im < 2; im++) {
                    mma_f16(ax[im][jn], ah[im][0], ah[im][1], ah[im][2], ah[im][3], b0, b1);
                    mma_f16(ax[im][jn], ah[im][0], ah[im][1], ah[im][2], ah[im][3], l0_, l1_);
                    mma_f16(ax[im][jn], al[im][0], al[im][1], al[im][2], al[im][3], b0, b1);
                }
                b0 = *(unsigned*)&B2h[nr][ks + 2 * c]; b1 = *(unsigned*)&B2h[nr][ks + 2 * c + 8];
                l0_ = *(unsigned*)&B2l[nr][ks + 2 * c]; l1_ = *(unsigned*)&B2l[nr][ks + 2 * c + 8];
                #pragma unroll
                for (int im = 0; im < 2; im++) {
                    mma_f16(aw[im][jn], ah[im][0], ah[im][1], ah[im][2], ah[im][3], b0, b1);
                    mma_f16(aw[im][jn], ah[im][0], ah[im][1], ah[im][2], ah[im][3], l0_, l1_);
                    mma_f16(aw[im][jn], al[im][0], al[im][1], al[im][2], al[im][3], b0, b1);
                }
            }
        }
    }
    float* hid = g_hidden + bh * CDSZ;
    float* dpr = g_dpre   + bh * CDSZ;
    float* dgp = g_dg     + bh * CDSZ;
    #pragma unroll
    for (int im = 0; im < 2; im++)
        #pragma unroll
        for (int jn = 0; jn < 4; jn++) {
            #pragma unroll
            for (int q = 0; q < 4; q++) {
                int row = c0 + wm + im * 16 + g + ((q >> 1) ? 8 : 0);
                int col = e0 + wn + jn * 8 + 2 * c + (q & 1);
                float gate = ag[im][jn][q], gg = ax[im][jn][q];
                float sg = 1.f / (1.f + __expf(-gate));
                float hs = gate * sg;
                float dhid = -aw[im][jn][q];
                int idx = row * DINL + col;
                hid[idx] = hs * gg;
                dgp[idx] = dhid * hs;
                dpr[idx] = dhid * gg * (sg + gate * sg * (1.f - sg));
            }
        }
}

// ---------------- LaCT weight grads + SGD (mma, transposed operand fills) ----------------
__global__ __launch_bounds__(256) void lact_dw_mma(const float* __restrict__ w0,
                                                   const float* __restrict__ w1,
                                                   const float* __restrict__ w2) {
    __shared__ __half Ah[128][LPAD], Al[128][LPAD], Bh[64][LPAD], Bl[64][LPAD];
    int z = blockIdx.z;
    int mode = z % 3, bh = z / 3;
    int n = bh >> 2, h = bh & 3;
    int i0 = blockIdx.y * 128, j0 = blockIdx.x * 64;
    const float* Xp = g_xn + n * CHK * HSZ + h * DINL;
    const float *P, *Q, *wb;
    float* wo;
    int ldP, ldQ;
    float sign;
    if (mode == 0)      { P = g_dpre + bh * CDSZ; ldP = DINL; Q = Xp; ldQ = HSZ;
                          wb = w0 + h * DINL * DINL; wo = g_w0n + bh * DINL * DINL; sign = -1.f; }
    else if (mode == 1) { P = g_dg + bh * CDSZ; ldP = DINL; Q = Xp; ldQ = HSZ;
                          wb = w2 + h * DINL * DINL; wo = g_w2n + bh * DINL * DINL; sign = -1.f; }
    else                { P = Xp; ldP = HSZ; Q = g_hidden + bh * CDSZ; ldQ = DINL;
                          wb = w1 + h * DINL * DINL; wo = g_w1n + bh * DINL * DINL; sign = 1.f; }
    int tid = threadIdx.x, wid = tid >> 5, lane = tid & 31;
    int g = lane >> 2, c = lane & 3;
    int wm = (wid & 3) * 32, wn = (wid >> 2) * 32;
    float acc[2][4][4] = {};

    for (int k0 = 0; k0 < CHK; k0 += 32) {
        __syncthreads();
        #pragma unroll
        for (int p = 0; p < 16; p++) {          // A^T fill
            int idx = tid + p * 256;
            int kk = idx >> 7, ii = idx & 127;
            float v = P[(k0 + kk) * ldP + i0 + ii];
            __half hv, lv; split_h(v, hv, lv);
            Ah[ii][kk] = hv; Al[ii][kk] = lv;
        }
        #pragma unroll
        for (int p = 0; p < 8; p++) {           // B^T fill
            int idx = tid + p * 256;
            int kk = idx >> 6, jj = idx & 63;
            float v = Q[(k0 + kk) * ldQ + j0 + jj];
            __half hv, lv; split_h(v, hv, lv);
            Bh[jj][kk] = hv; Bl[jj][kk] = lv;
        }
        __syncthreads();
        #pragma unroll
        for (int ks = 0; ks < 32; ks += 16) {
            unsigned ah[2][4], al[2][4];
            #pragma unroll
            for (int im = 0; im < 2; im++) {
                int mr = wm + im * 16;
                ah[im][0] = *(unsigned*)&Ah[mr + g][ks + 2 * c];
                ah[im][1] = *(unsigned*)&Ah[mr + g + 8][ks + 2 * c];
                ah[im][2] = *(unsigned*)&Ah[mr + g][ks + 2 * c + 8];
                ah[im][3] = *(unsigned*)&Ah[mr + g + 8][ks + 2 * c + 8];
                al[im][0] = *(unsigned*)&Al[mr + g][ks + 2 * c];
                al[im][1] = *(unsigned*)&Al[mr + g + 8][ks + 2 * c];
                al[im][2] = *(unsigned*)&Al[mr + g][ks + 2 * c + 8];
                al[im][3] = *(unsigned*)&Al[mr + g + 8][ks + 2 * c + 8];
            }
            #pragma unroll
            for (int jn = 0; jn < 4; jn++) {
                int nr = wn + jn * 8 + g;
                unsigned b0 = *(unsigned*)&Bh[nr][ks + 2 * c];
                unsigned b1 = *(unsigned*)&Bh[nr][ks + 2 * c + 8];
                unsigned l0_ = *(unsigned*)&Bl[nr][ks + 2 * c];
                unsigned l1_ = *(unsigned*)&Bl[nr][ks + 2 * c + 8];
                #pragma unroll
                for (int im = 0; im < 2; im++) {
                    mma_f16(acc[im][jn], ah[im][0], ah[im][1], ah[im][2], ah[im][3], b0, b1);
                    mma_f16(acc[im][jn], ah[im][0], ah[im][1], ah[im][2], ah[im][3], l0_, l1_);
                    mma_f16(acc[im][jn], al[im][0], al[im][1], al[im][2], al[im][3], b0, b1);
                }
            }
        }
    }
    #pragma unroll
    for (int im = 0; im < 2; im++)
        #pragma unroll
        for (int jn = 0; jn < 4; jn++) {
            int row = i0 + wm + im * 16 + g;
            int col = j0 + wn + jn * 8 + 2 * c;
            wo[row * DINL + col]           = wb[row * DINL + col]           + sign * acc[im][jn][0];
            wo[row * DINL + col + 1]       = wb[row * DINL + col + 1]       + sign * acc[im][jn][1];
            wo[(row + 8) * DINL + col]     = wb[(row + 8) * DINL + col]     + sign * acc[im][jn][2];
            wo[(row + 8) * DINL + col + 1] = wb[(row + 8) * DINL + col + 1] + sign * acc[im][jn][3];
        }
}

// ---------------- LaCT apply1 (mma): u = silu(X w0n^T) * (X w2n^T) ----------------
__global__ __launch_bounds__(256) void lact_apply1_mma() {
    __shared__ __half Ah[128][LPAD], Al[128][LPAD];
    __shared__ __half B0h[64][LPAD], B0l[64][LPAD], B1h[64][LPAD], B1l[64][LPAD];
    int bh = blockIdx.z, n = bh >> 2, h = bh & 3;
    int e0 = blockIdx.x * 64, c0 = blockIdx.y * 128;
    const float* X  = g_xn + n * CHK * HSZ + h * DINL;
    const float* wa = g_w0n + bh * DINL * DINL;
    const float* wc = g_w2n + bh * DINL * DINL;
    int tid = threadIdx.x, wid = tid >> 5, lane = tid & 31;
    int g = lane >> 2, c = lane & 3;
    int wm = (wid & 3) * 32, wn = (wid >> 2) * 32;
    float a0[2][4][4] = {}, a2[2][4][4] = {};

    for (int k0 = 0; k0 < DINL; k0 += 32) {
        __syncthreads();
        #pragma unroll
        for (int p = 0; p < 8; p++) {
            int idx = tid + p * 256;
            int r = idx >> 4, cc = (idx & 15) * 2;
            const float* s = X + (c0 + r) * HSZ + k0 + cc;
            unsigned hh, ll;
            split_pack_h(s[0], s[1], hh, ll);
            *(unsigned*)&Ah[r][cc] = hh; *(unsigned*)&Al[r][cc] = ll;
        }
        #pragma unroll
        for (int p = 0; p < 4; p++) {
            int idx = tid + p * 256;
            int r = idx >> 4, cc = (idx & 15) * 2;
            unsigned hh, ll;
            const float* sa = wa + (e0 + r) * DINL + k0 + cc;
            split_pack_h(sa[0], sa[1], hh, ll);
            *(unsigned*)&B0h[r][cc] = hh; *(unsigned*)&B0l[r][cc] = ll;
            const float* sc = wc + (e0 + r) * DINL + k0 + cc;
            split_pack_h(sc[0], sc[1], hh, ll);
            *(unsigned*)&B1h[r][cc] = hh; *(unsigned*)&B1l[r][cc] = ll;
        }
        __syncthreads();
        #pragma unroll
        for (int ks = 0; ks < 32; ks += 16) {
            unsigned ah[2][4], al[2][4];
            #pragma unroll
            for (int im = 0; im < 2; im++) {
                int mr = wm + im * 16;
                ah[im][0] = *(unsigned*)&Ah[mr + g][ks + 2 * c];
                ah[im][1] = *(unsigned*)&Ah[mr + g + 8][ks + 2 * c];
                ah[im][2] = *(unsigned*)&Ah[mr + g][ks + 2 * c + 8];
                ah[im][3] = *(unsigned*)&Ah[mr + g + 8][ks + 2 * c + 8];
                al[im][0] = *(unsigned*)&Al[mr + g][ks + 2 * c];
                al[im][1] = *(unsigned*)&Al[mr + g + 8][ks + 2 * c];
                al[im][2] = *(unsigned*)&Al[mr + g][ks + 2 * c + 8];
                al[im][3] = *(unsigned*)&Al[mr + g + 8][ks + 2 * c + 8];
            }
            #pragma unroll
            for (int jn = 0; jn < 4; jn++) {
                int nr = wn + jn * 8 + g;
                unsigned b0, b1, l0_, l1_;
                b0 = *(unsigned*)&B0h[nr][ks + 2 * c]; b1 = *(unsigned*)&B0h[nr][ks + 2 * c + 8];
                l0_ = *(unsigned*)&B0l[nr][ks + 2 * c]; l1_ = *(unsigned*)&B0l[nr][ks + 2 * c + 8];
                #pragma unroll
                for (int im = 0; im < 2; im++) {
                    mma_f16(a0[im][jn], ah[im][0], ah[im][1], ah[im][2], ah[im][3], b0, b1);
                    mma_f16(a0[im][jn], ah[im][0], ah[im][1], ah[im][2], ah[im][3], l0_, l1_);
                    mma_f16(a0[im][jn], al[im][0], al[im][1], al[im][2], al[im][3], b0, b1);
                }
                b0 = *(unsigned*)&B1h[nr][ks + 2 * c]; b1 = *(unsigned*)&B1h[nr][ks + 2 * c + 8];
                l0_ = *(unsigned*)&B1l[nr][ks + 2 * c]; l1_ = *(unsigned*)&B1l[nr][ks + 2 * c + 8];
                #pragma unroll
                for (int im = 0; im < 2; im++) {
                    mma_f16(a2[im][jn], ah[im][0], ah[im][1], ah[im][2], ah[im][3], b0, b1);
                    mma_f16(a2[im][jn], ah[im][0], ah[im][1], ah[im][2], ah[im][3], l0_, l1_);
                    mma_f16(a2[im][jn], al[im][0], al[im][1], al[im][2], al[im][3], b0, b1);
                }
            }
        }
    }
    float* up = g_u + bh * CDSZ;
    #pragma unroll
    for (int im = 0; im < 2; im++)
        #pragma unroll
        for (int jn = 0; jn < 4; jn++) {
            #pragma unroll
            for (int q = 0; q < 4; q++) {
                int row = c0 + wm + im * 16 + g + ((q >> 1) ? 8 : 0);
                int col = e0 + wn + jn * 8 + 2 * c + (q & 1);
                float gq = a0[im][jn][q];
                float sg = 1.f / (1.f + __expf(-gq));
                // store pre-scaled by 2^-12 so apply2's fp16 split cannot overflow
                up[row * DINL + col] = (gq * sg * a2[im][jn][q]) * USCALE;
            }
        }
}

// ---------------- LaCT apply2 (mma): out += (u_scaled @ w1n^T) * 2^12 ----------------
__global__ __launch_bounds__(256) void lact_apply2_mma(float* __restrict__ out) {
    __shared__ __half Ah[128][LPAD], Al[128][LPAD], Bh[64][LPAD], Bl[64][LPAD];
    int bh = blockIdx.z, n = bh >> 2, h = bh & 3;
    int d0 = blockIdx.x * 64, c0 = blockIdx.y * 128;
    const float* U   = g_u + bh * CDSZ;
    const float* w1n = g_w1n + bh * DINL * DINL;
    int tid = threadIdx.x, wid = tid >> 5, lane = tid & 31;
    int g = lane >> 2, c = lane & 3;
    int wm = (wid & 3) * 32, wn = (wid >> 2) * 32;
    float acc[2][4][4] = {};

    for (int k0 = 0; k0 < DINL; k0 += 32) {
        __syncthreads();
        #pragma unroll
        for (int p = 0; p < 8; p++) {
            int idx = tid + p * 256;
            int r = idx >> 4, cc = (idx & 15) * 2;
            const float* s = U + (c0 + r) * DINL + k0 + cc;
            unsigned hh, ll;
            split_pack_h(s[0], s[1], hh, ll);
            *(unsigned*)&Ah[r][cc] = hh; *(unsigned*)&Al[r][cc] = ll;
        }
        #pragma unroll
        for (int p = 0; p < 4; p++) {
            int idx = tid + p * 256;
            int r = idx >> 4, cc = (idx & 15) * 2;
            const float* s = w1n + (d0 + r) * DINL + k0 + cc;
            unsigned hh, ll;
            split_pack_h(s[0], s[1], hh, ll);
            *(unsigned*)&Bh[r][cc] = hh; *(unsigned*)&Bl[r][cc] = ll;
        }
        __syncthreads();
        #pragma unroll
        for (int ks = 0; ks < 32; ks += 16) {
            unsigned ah[2][4], al[2][4];
            #pragma unroll
            for (int im = 0; im < 2; im++) {
                int mr = wm + im * 16;
                ah[im][0] = *(unsigned*)&Ah[mr + g][ks + 2 * c];
                ah[im][1] = *(unsigned*)&Ah[mr + g + 8][ks + 2 * c];
                ah[im][2] = *(unsigned*)&Ah[mr + g][ks + 2 * c + 8];
                ah[im][3] = *(unsigned*)&Ah[mr + g + 8][ks + 2 * c + 8];
                al[im][0] = *(unsigned*)&Al[mr + g][ks + 2 * c];
                al[im][1] = *(unsigned*)&Al[mr + g + 8][ks + 2 * c];
                al[im][2] = *(unsigned*)&Al[mr + g][ks + 2 * c + 8];
                al[im][3] = *(unsigned*)&Al[mr + g + 8][ks + 2 * c + 8];
            }
            #pragma unroll
            for (int jn = 0; jn < 4; jn++) {
                int nr = wn + jn * 8 + g;
                unsigned b0 = *(unsigned*)&Bh[nr][ks + 2 * c];
                unsigned b1 = *(unsigned*)&Bh[nr][ks + 2 * c + 8];
                unsigned l0_ = *(unsigned*)&Bl[nr][ks + 2 * c];
                unsigned l1_ = *(unsigned*)&Bl[nr][ks + 2 * c + 8];
                #pragma unroll
                for (int im = 0; im < 2; im++) {
                    mma_f16(acc[im][jn], ah[im][0], ah[im][1], ah[im][2], ah[im][3], b0, b1);
                    mma_f16(acc[im][jn], ah[im][0], ah[im][1], ah[im][2], ah[im][3], l0_, l1_);
                    mma_f16(acc[im][jn], al[im][0], al[im][1], al[im][2], al[im][3], b0, b1);
                }
            }
        }
    }
    #pragma unroll
    for (int im = 0; im < 2; im++)
        #pragma unroll
        for (int jn = 0; jn < 4; jn++) {
            #pragma unroll
            for (int q = 0; q < 4; q++) {
                int row = c0 + wm + im * 16 + g + ((q >> 1) ? 8 : 0);
                int col = d0 + wn + jn * 8 + 2 * c + (q & 1);
                out[(n * CHK + row) * HSZ + h * DINL + col] += acc[im][jn][q] * USCALE_INV;
            }
        }
}

// ---------------- launch ----------------
extern "C" void kernel_launch(void* const* d_in, const int* in_sizes, int n_in,
                              void* d_out, int out_size) {
    const float* x   = (const float*)d_in[0];
    const float* lnw = (const float*)d_in[1];
    const float* lnb = (const float*)d_in[2];
    const float* ipw = (const float*)d_in[3];
    const float* ipb = (const float*)d_in[4];
    const float* opw = (const float*)d_in[5];
    const float* opb = (const float*)d_in[6];
    const float* w0  = (const float*)d_in[7];
    const float* w1  = (const float*)d_in[8];
    const float* w2  = (const float*)d_in[9];
    float* out = (float*)d_out;

    ln_kernel<<<SQ, 256>>>(x, lnw, lnb);
    gemm_mma_kernel<<<dim3(3 * HSZ / 64, SQ / 128), 256>>>(ipw, ipb, nullptr, 0, 3 * HSZ, HSZ);
    cvt_k_kernel<<<dim3(SQ / 64, NHA), 256>>>();
    cvt_v_kernel<<<dim3(SQ / 64, NHA), 256>>>();
    attn_mma_kernel<<<dim3(SQ / 128, NHA), 256>>>();
    gemm_mma_kernel<<<dim3(HSZ / 64, SQ / 128), 256>>>(opw, opb, out, 1, HSZ, HSZ);
    lact_fwd_mma<<<dim3(DINL / 64, CHK / 128, NBH), 256>>>(w0, w1, w2);
    lact_dw_mma<<<dim3(DINL / 64, DINL / 128, NBH * 3), 256>>>(w0, w1, w2);
    lact_apply1_mma<<<dim3(DINL / 64, CHK / 128, NBH), 256>>>();
    lact_apply2_mma<<<dim3(DINL / 64, CHK / 128, NBH), 256>>>(out);
}

// round 6
// speedup vs baseline: 6.4065x; 1.3953x over previous
#include <cuda_runtime.h>
#include <cuda_fp16.h>
#include <cuda_bf16.h>
#include <math.h>

// ---------------- problem constants ----------------
#define SQ    4096
#define HSZ   1024
#define NHA   16
#define HD    64
#define NHL   4
#define DINL  256
#define CHK   1024
#define NCH   4
#define NBH   16
#define CDSZ  (CHK*DINL)
#define WSZ   (DINL*DINL)

#define USCALE     2.44140625e-4f   // 2^-12
#define USCALE_INV 4096.0f

// ---------------- scratch ----------------
__device__ float g_xn[SQ*HSZ];
__device__ float g_qkv[SQ*3*HSZ];
__device__ float g_ao[SQ*HSZ];
__device__ float g_hidden[NBH*CDSZ];
__device__ float g_dpre[NBH*CDSZ];
__device__ float g_dg[NBH*CDSZ];
// attention fp16 (single precision) K [h][s][64perm], V^T [h][d][SQ perm]
__device__ __half g_kh[NHA*SQ*HD];
__device__ __half g_vh[NHA*HD*SQ];
// lact precomputed fp16 splits
__device__ __half g_xh[SQ*HSZ],  g_xl[SQ*HSZ];          // X row-major
__device__ __half g_xth[NBH*DINL*CHK], g_xtl[NBH*DINL*CHK]; // X^T per (n,h): [d][c]
__device__ __half g_w0h[NHL*WSZ], g_w0l[NHL*WSZ];
__device__ __half g_w2h[NHL*WSZ], g_w2l[NHL*WSZ];
__device__ __half g_w1th[NHL*WSZ], g_w1tl[NHL*WSZ];     // w1^T: [e][d]
__device__ __half g_w0nh[NBH*WSZ], g_w0nl[NBH*WSZ];
__device__ __half g_w1nh[NBH*WSZ], g_w1nl[NBH*WSZ];     // native [d][e]
__device__ __half g_w2nh[NBH*WSZ], g_w2nl[NBH*WSZ];
__device__ __half g_uh[NBH*CDSZ], g_ul[NBH*CDSZ];       // u pre-scaled 2^-12

// ---------------- mma helpers ----------------
__device__ __forceinline__ void mma_bf16(float c[4],
                                         unsigned a0, unsigned a1, unsigned a2, unsigned a3,
                                         unsigned b0, unsigned b1) {
    asm volatile(
        "mma.sync.aligned.m16n8k16.row.col.f32.bf16.bf16.f32 "
        "{%0,%1,%2,%3}, {%4,%5,%6,%7}, {%8,%9}, {%0,%1,%2,%3};\n"
        : "+f"(c[0]), "+f"(c[1]), "+f"(c[2]), "+f"(c[3])
        : "r"(a0), "r"(a1), "r"(a2), "r"(a3), "r"(b0), "r"(b1));
}
__device__ __forceinline__ void mma_f16(float c[4],
                                        unsigned a0, unsigned a1, unsigned a2, unsigned a3,
                                        unsigned b0, unsigned b1) {
    asm volatile(
        "mma.sync.aligned.m16n8k16.row.col.f32.f16.f16.f32 "
        "{%0,%1,%2,%3}, {%4,%5,%6,%7}, {%8,%9}, {%0,%1,%2,%3};\n"
        : "+f"(c[0]), "+f"(c[1]), "+f"(c[2]), "+f"(c[3])
        : "r"(a0), "r"(a1), "r"(a2), "r"(a3), "r"(b0), "r"(b1));
}
__device__ __forceinline__ void split_pack_bf(float x, float y, unsigned &h, unsigned &l) {
    __nv_bfloat16 hx = __float2bfloat16_rn(x), hy = __float2bfloat16_rn(y);
    __nv_bfloat162 H; H.x = hx; H.y = hy;
    h = *reinterpret_cast<unsigned*>(&H);
    __nv_bfloat162 L;
    L.x = __float2bfloat16_rn(x - __bfloat162float(hx));
    L.y = __float2bfloat16_rn(y - __bfloat162float(hy));
    l = *reinterpret_cast<unsigned*>(&L);
}
__device__ __forceinline__ void split_pack_h(float x, float y, unsigned &h, unsigned &l) {
    __half hx = __float2half_rn(x), hy = __float2half_rn(y);
    __half2 H = __halves2half2(hx, hy);
    h = *reinterpret_cast<unsigned*>(&H);
    __half2 L = __halves2half2(__float2half_rn(x - __half2float(hx)),
                               __float2half_rn(y - __half2float(hy)));
    l = *reinterpret_cast<unsigned*>(&L);
}
__device__ __forceinline__ void split_h(float x, __half &h, __half &l) {
    h = __float2half_rn(x);
    l = __float2half_rn(x - __half2float(h));
}
__device__ __forceinline__ unsigned packh(float x, float y) {
    __half2 t = __float22half2_rn(make_float2(x, y));
    return *reinterpret_cast<unsigned*>(&t);
}

// ---------------- LayerNorm ----------------
__global__ __launch_bounds__(256) void ln_kernel(const float* __restrict__ x,
                                                 const float* __restrict__ w,
                                                 const float* __restrict__ b) {
    int row = blockIdx.x;
    const float* xr = x + row * HSZ;
    float* o = g_xn + row * HSZ;
    __shared__ float red[64];
    float s = 0.f, s2 = 0.f;
    for (int i = threadIdx.x; i < HSZ; i += 256) {
        float v = xr[i];
        s += v; s2 += v * v;
    }
    #pragma unroll
    for (int off = 16; off; off >>= 1) {
        s  += __shfl_down_sync(~0u, s,  off);
        s2 += __shfl_down_sync(~0u, s2, off);
    }
    int wid = threadIdx.x >> 5, lid = threadIdx.x & 31;
    if (lid == 0) { red[wid] = s; red[wid + 32] = s2; }
    __syncthreads();
    if (threadIdx.x == 0) {
        float ts = 0.f, ts2 = 0.f;
        for (int i = 0; i < 8; i++) { ts += red[i]; ts2 += red[i + 32]; }
        red[0] = ts / HSZ;
        red[1] = ts2 / HSZ;
    }
    __syncthreads();
    float mu  = red[0];
    float var = red[1] - mu * mu;
    float inv = rsqrtf(var + 1e-5f);
    for (int i = threadIdx.x; i < HSZ; i += 256) {
        o[i] = (xr[i] - mu) * inv * w[i] + b[i];
    }
}

// ---------------- big projections (split-bf16 mma, proven) ----------------
__global__ __launch_bounds__(256) void gemm_mma_kernel(const float* __restrict__ Bw,
                                                       const float* __restrict__ bias,
                                                       float* __restrict__ Cext,
                                                       int which, int N, int K) {
    const float* A = (which == 0) ? g_xn : g_ao;
    float* C = (which == 0) ? g_qkv : Cext;
    __shared__ __nv_bfloat16 Ah[128][40], Al[128][40], Bh[64][40], Bl[64][40];
    int n0 = blockIdx.x * 64, m0 = blockIdx.y * 128;
    int tid = threadIdx.x;
    int wid = tid >> 5, lane = tid & 31;
    int g = lane >> 2, c = lane & 3;
    int wm = (wid & 3) * 32, wn = (wid >> 2) * 32;
    float acc[2][4][4];
    #pragma unroll
    for (int i = 0; i < 2; i++)
        #pragma unroll
        for (int j = 0; j < 4; j++)
            #pragma unroll
            for (int q = 0; q < 4; q++) acc[i][j][q] = 0.f;

    for (int k0 = 0; k0 < K; k0 += 32) {
        __syncthreads();
        #pragma unroll
        for (int p = 0; p < 4; p++) {
            int idx = tid + p * 256;
            int r = idx >> 3, cc = (idx & 7) * 4;
            float4 v = *(const float4*)(A + (m0 + r) * K + k0 + cc);
            unsigned hh, ll;
            split_pack_bf(v.x, v.y, hh, ll);
            *(unsigned*)&Ah[r][cc] = hh; *(unsigned*)&Al[r][cc] = ll;
            split_pack_bf(v.z, v.w, hh, ll);
            *(unsigned*)&Ah[r][cc + 2] = hh; *(unsigned*)&Al[r][cc + 2] = ll;
        }
        #pragma unroll
        for (int p = 0; p < 2; p++) {
            int idx = tid + p * 256;
            int r = idx >> 3, cc = (idx & 7) * 4;
            float4 v = *(const float4*)(Bw + (n0 + r) * K + k0 + cc);
            unsigned hh, ll;
            split_pack_bf(v.x, v.y, hh, ll);
            *(unsigned*)&Bh[r][cc] = hh; *(unsigned*)&Bl[r][cc] = ll;
            split_pack_bf(v.z, v.w, hh, ll);
            *(unsigned*)&Bh[r][cc + 2] = hh; *(unsigned*)&Bl[r][cc + 2] = ll;
        }
        __syncthreads();
        #pragma unroll
        for (int ks = 0; ks < 32; ks += 16) {
            unsigned ah[2][4], al[2][4];
            #pragma unroll
            for (int im = 0; im < 2; im++) {
                int mr = wm + im * 16;
                ah[im][0] = *(unsigned*)&Ah[mr + g][ks + 2 * c];
                ah[im][1] = *(unsigned*)&Ah[mr + g + 8][ks + 2 * c];
                ah[im][2] = *(unsigned*)&Ah[mr + g][ks + 2 * c + 8];
                ah[im][3] = *(unsigned*)&Ah[mr + g + 8][ks + 2 * c + 8];
                al[im][0] = *(unsigned*)&Al[mr + g][ks + 2 * c];
                al[im][1] = *(unsigned*)&Al[mr + g + 8][ks + 2 * c];
                al[im][2] = *(unsigned*)&Al[mr + g][ks + 2 * c + 8];
                al[im][3] = *(unsigned*)&Al[mr + g + 8][ks + 2 * c + 8];
            }
            #pragma unroll
            for (int jn = 0; jn < 4; jn++) {
                int nr = wn + jn * 8 + g;
                unsigned b0 = *(unsigned*)&Bh[nr][ks + 2 * c];
                unsigned b1 = *(unsigned*)&Bh[nr][ks + 2 * c + 8];
                unsigned l0 = *(unsigned*)&Bl[nr][ks + 2 * c];
                unsigned l1 = *(unsigned*)&Bl[nr][ks + 2 * c + 8];
                #pragma unroll
                for (int im = 0; im < 2; im++) {
                    mma_bf16(acc[im][jn], ah[im][0], ah[im][1], ah[im][2], ah[im][3], b0, b1);
                    mma_bf16(acc[im][jn], ah[im][0], ah[im][1], ah[im][2], ah[im][3], l0, l1);
                    mma_bf16(acc[im][jn], al[im][0], al[im][1], al[im][2], al[im][3], b0, b1);
                }
            }
        }
    }
    #pragma unroll
    for (int im = 0; im < 2; im++)
        #pragma unroll
        for (int jn = 0; jn < 4; jn++) {
            int row = m0 + wm + im * 16 + g;
            int col = n0 + wn + jn * 8 + 2 * c;
            float b0v = bias[col], b1v = bias[col + 1];
            C[row * N + col]           = acc[im][jn][0] + b0v;
            C[row * N + col + 1]       = acc[im][jn][1] + b1v;
            C[(row + 8) * N + col]     = acc[im][jn][2] + b0v;
            C[(row + 8) * N + col + 1] = acc[im][jn][3] + b1v;
        }
}

// ---------------- K/V fp16 precompute (mma-permuted k order, single precision) ----------------
__device__ __forceinline__ int permpos(int r) {  // r even
    int rr = r & 15;
    return (r & ~15) + ((rr & 7) >> 1) * 4 + ((rr >> 3) & 1) * 2;
}

__global__ __launch_bounds__(256) void cvt_k_kernel() {
    int h = blockIdx.y, s0 = blockIdx.x * 64;
    #pragma unroll
    for (int p = 0; p < 8; p++) {
        int idx = threadIdx.x + p * 256;
        int s = idx >> 5, d = (idx & 31) * 2;
        const float* src = g_qkv + (s0 + s) * (3 * HSZ) + HSZ + h * 64 + d;
        int pos = permpos(d);
        long base = ((long)(h * SQ) + s0 + s) * 64 + pos;
        *(unsigned*)(g_kh + base) = packh(src[0], src[1]);
    }
}

__global__ __launch_bounds__(256) void cvt_v_kernel() {
    __shared__ float ts[64][65];
    int h = blockIdx.y, s0 = blockIdx.x * 64;
    #pragma unroll
    for (int p = 0; p < 16; p++) {
        int idx = threadIdx.x + p * 256;
        int s = idx >> 6, d = idx & 63;
        ts[s][d] = g_qkv[(s0 + s) * (3 * HSZ) + 2 * HSZ + h * 64 + d];
    }
    __syncthreads();
    #pragma unroll
    for (int p = 0; p < 8; p++) {
        int idx = threadIdx.x + p * 256;
        int d = idx >> 5, sp = (idx & 31) * 2;
        int pos = permpos(sp);
        long base = ((long)(h * 64) + d) * SQ + s0 + pos;
        *(unsigned*)(g_vh + base) = packh(ts[sp][d], ts[sp + 1][d]);
    }
}

// ---------------- fp16 flash attention: 8 warps x 32 q-rows, shared B frags ----------------
#define KSTR 72
__global__ __launch_bounds__(256) void attn2_kernel() {
    __shared__ __half Kh[64][KSTR], Vh[64][KSTR];
    int h = blockIdx.y, qt = blockIdx.x;
    int tid = threadIdx.x, w = tid >> 5, lane = tid & 31;
    int g = lane >> 2, c = lane & 3;
    int qr = qt * 256 + w * 32;

    unsigned q[2][4][4];
    #pragma unroll
    for (int mt = 0; mt < 2; mt++) {
        const float* p0 = g_qkv + (qr + mt * 16 + g) * (3 * HSZ) + h * HD;
        const float* p1 = p0 + 8 * (3 * HSZ);
        #pragma unroll
        for (int kt = 0; kt < 4; kt++) {
            int d0 = kt * 16 + 2 * c;
            q[mt][kt][0] = packh(p0[d0] * 0.125f,     p0[d0 + 1] * 0.125f);
            q[mt][kt][1] = packh(p1[d0] * 0.125f,     p1[d0 + 1] * 0.125f);
            q[mt][kt][2] = packh(p0[d0 + 8] * 0.125f, p0[d0 + 9] * 0.125f);
            q[mt][kt][3] = packh(p1[d0 + 8] * 0.125f, p1[d0 + 9] * 0.125f);
        }
    }

    float o[2][8][4];
    #pragma unroll
    for (int mt = 0; mt < 2; mt++)
        #pragma unroll
        for (int i = 0; i < 8; i++)
            #pragma unroll
            for (int j = 0; j < 4; j++) o[mt][i][j] = 0.f;
    float mM[2][2] = {{-1e30f, -1e30f}, {-1e30f, -1e30f}};
    float lL[2][2] = {{0.f, 0.f}, {0.f, 0.f}};

    for (int kb = 0; kb < SQ / 64; kb++) {
        __syncthreads();
        #pragma unroll
        for (int p = 0; p < 2; p++) {
            int idx = tid + p * 256;
            int r = idx >> 3, sg = idx & 7;
            *(uint4*)&Kh[r][sg * 8] = *(const uint4*)(g_kh + ((long)(h * SQ) + kb * 64 + r) * 64 + sg * 8);
            *(uint4*)&Vh[r][sg * 8] = *(const uint4*)(g_vh + ((long)(h * 64) + r) * SQ + kb * 64 + sg * 8);
        }
        __syncthreads();

        float s[2][8][4];
        #pragma unroll
        for (int mt = 0; mt < 2; mt++)
            #pragma unroll
            for (int i = 0; i < 8; i++)
                #pragma unroll
                for (int j = 0; j < 4; j++) s[mt][i][j] = 0.f;
        #pragma unroll
        for (int kt = 0; kt < 4; kt++)
            #pragma unroll
            for (int jn = 0; jn < 8; jn++) {
                uint2 b = *(const uint2*)&Kh[jn * 8 + g][kt * 16 + 4 * c];
                mma_f16(s[0][jn], q[0][kt][0], q[0][kt][1], q[0][kt][2], q[0][kt][3], b.x, b.y);
                mma_f16(s[1][jn], q[1][kt][0], q[1][kt][1], q[1][kt][2], q[1][kt][3], b.x, b.y);
            }

        #pragma unroll
        for (int mt = 0; mt < 2; mt++) {
            float mx0 = s[mt][0][0], mx1 = s[mt][0][2];
            #pragma unroll
            for (int jn = 0; jn < 8; jn++) {
                mx0 = fmaxf(mx0, fmaxf(s[mt][jn][0], s[mt][jn][1]));
                mx1 = fmaxf(mx1, fmaxf(s[mt][jn][2], s[mt][jn][3]));
            }
            mx0 = fmaxf(mx0, __shfl_xor_sync(~0u, mx0, 1));
            mx0 = fmaxf(mx0, __shfl_xor_sync(~0u, mx0, 2));
            mx1 = fmaxf(mx1, __shfl_xor_sync(~0u, mx1, 1));
            mx1 = fmaxf(mx1, __shfl_xor_sync(~0u, mx1, 2));
            float nm0 = fmaxf(mM[mt][0], mx0), nm1 = fmaxf(mM[mt][1], mx1);
            float cr0 = __expf(mM[mt][0] - nm0), cr1 = __expf(mM[mt][1] - nm1);
            lL[mt][0] *= cr0; lL[mt][1] *= cr1;
            #pragma unroll
            for (int dn = 0; dn < 8; dn++) {
                o[mt][dn][0] *= cr0; o[mt][dn][1] *= cr0;
                o[mt][dn][2] *= cr1; o[mt][dn][3] *= cr1;
            }
            float ps0 = 0.f, ps1 = 0.f;
            #pragma unroll
            for (int jn = 0; jn < 8; jn++) {
                s[mt][jn][0] = __expf(s[mt][jn][0] - nm0);
                s[mt][jn][1] = __expf(s[mt][jn][1] - nm0);
                s[mt][jn][2] = __expf(s[mt][jn][2] - nm1);
                s[mt][jn][3] = __expf(s[mt][jn][3] - nm1);
                ps0 += s[mt][jn][0] + s[mt][jn][1];
                ps1 += s[mt][jn][2] + s[mt][jn][3];
            }
            lL[mt][0] += ps0; lL[mt][1] += ps1;
            mM[mt][0] = nm0; mM[mt][1] = nm1;
        }

        #pragma unroll
        for (int kt = 0; kt < 4; kt++) {
            unsigned p0h[4], p1h[4];
            p0h[0] = packh(s[0][2 * kt][0],     s[0][2 * kt][1]);
            p0h[1] = packh(s[0][2 * kt][2],     s[0][2 * kt][3]);
            p0h[2] = packh(s[0][2 * kt + 1][0], s[0][2 * kt + 1][1]);
            p0h[3] = packh(s[0][2 * kt + 1][2], s[0][2 * kt + 1][3]);
            p1h[0] = packh(s[1][2 * kt][0],     s[1][2 * kt][1]);
            p1h[1] = packh(s[1][2 * kt][2],     s[1][2 * kt][3]);
            p1h[2] = packh(s[1][2 * kt + 1][0], s[1][2 * kt + 1][1]);
            p1h[3] = packh(s[1][2 * kt + 1][2], s[1][2 * kt + 1][3]);
            #pragma unroll
            for (int dn = 0; dn < 8; dn++) {
                uint2 v = *(const uint2*)&Vh[dn * 8 + g][kt * 16 + 4 * c];
                mma_f16(o[0][dn], p0h[0], p0h[1], p0h[2], p0h[3], v.x, v.y);
                mma_f16(o[1][dn], p1h[0], p1h[1], p1h[2], p1h[3], v.x, v.y);
            }
        }
    }

    #pragma unroll
    for (int mt = 0; mt < 2; mt++) {
        float l0 = lL[mt][0], l1 = lL[mt][1];
        l0 += __shfl_xor_sync(~0u, l0, 1); l0 += __shfl_xor_sync(~0u, l0, 2);
        l1 += __shfl_xor_sync(~0u, l1, 1); l1 += __shfl_xor_sync(~0u, l1, 2);
        float i0 = 1.f / l0, i1 = 1.f / l1;
        int r0 = qr + mt * 16 + g;
        #pragma unroll
        for (int dn = 0; dn < 8; dn++) {
            int col = h * HD + dn * 8 + 2 * c;
            g_ao[r0 * HSZ + col]           = o[mt][dn][0] * i0;
            g_ao[r0 * HSZ + col + 1]       = o[mt][dn][1] * i0;
            g_ao[(r0 + 8) * HSZ + col]     = o[mt][dn][2] * i1;
            g_ao[(r0 + 8) * HSZ + col + 1] = o[mt][dn][3] * i1;
        }
    }
}

// ---------------- lact split precompute ----------------
__global__ __launch_bounds__(256) void cvt_x_kernel() {
    int i4 = (blockIdx.x * 256 + threadIdx.x) * 4;
    float4 v = *(const float4*)(g_xn + i4);
    unsigned h0, l0, h1, l1;
    split_pack_h(v.x, v.y, h0, l0);
    split_pack_h(v.z, v.w, h1, l1);
    *(uint2*)(g_xh + i4) = make_uint2(h0, h1);
    *(uint2*)(g_xl + i4) = make_uint2(l0, l1);
}

__global__ __launch_bounds__(256) void cvt_xt_kernel() {
    __shared__ float ts[64][65];
    int bh = blockIdx.z, n = bh >> 2, h = bh & 3;
    int c0 = blockIdx.x * 64, d0 = blockIdx.y * 64;
    int tid = threadIdx.x;
    #pragma unroll
    for (int p = 0; p < 16; p++) {
        int idx = tid + p * 256;
        int cc = idx >> 6, dd = idx & 63;
        ts[cc][dd] = g_xn[(n * CHK + c0 + cc) * HSZ + h * DINL + d0 + dd];
    }
    __syncthreads();
    #pragma unroll
    for (int p = 0; p < 8; p++) {
        int idx = tid + p * 256;
        int d = idx >> 5, cp = (idx & 31) * 2;
        unsigned hh, ll;
        split_pack_h(ts[cp][d], ts[cp + 1][d], hh, ll);
        int base = (bh * DINL + d0 + d) * CHK + c0 + cp;
        *(unsigned*)(g_xth + base) = hh;
        *(unsigned*)(g_xtl + base) = ll;
    }
}

__global__ __launch_bounds__(256) void cvt_w_kernel(const float* __restrict__ w0,
                                                    const float* __restrict__ w2) {
    int i4 = (blockIdx.x * 256 + threadIdx.x) * 4;
    float4 v = *(const float4*)(w0 + i4);
    unsigned h0, l0, h1, l1;
    split_pack_h(v.x, v.y, h0, l0); split_pack_h(v.z, v.w, h1, l1);
    *(uint2*)(g_w0h + i4) = make_uint2(h0, h1);
    *(uint2*)(g_w0l + i4) = make_uint2(l0, l1);
    v = *(const float4*)(w2 + i4);
    split_pack_h(v.x, v.y, h0, l0); split_pack_h(v.z, v.w, h1, l1);
    *(uint2*)(g_w2h + i4) = make_uint2(h0, h1);
    *(uint2*)(g_w2l + i4) = make_uint2(l0, l1);
}

__global__ __launch_bounds__(256) void cvt_w1t_kernel(const float* __restrict__ w1) {
    __shared__ float ts[64][65];
    int h = blockIdx.z;
    int d0 = blockIdx.x * 64, e0 = blockIdx.y * 64;
    int tid = threadIdx.x;
    #pragma unroll
    for (int p = 0; p < 16; p++) {
        int idx = tid + p * 256;
        int dd = idx >> 6, ee = idx & 63;
        ts[dd][ee] = w1[h * WSZ + (d0 + dd) * DINL + e0 + ee];
    }
    __syncthreads();
    #pragma unroll
    for (int p = 0; p < 8; p++) {
        int idx = tid + p * 256;
        int e = idx >> 5, dp = (idx & 31) * 2;
        unsigned hh, ll;
        split_pack_h(ts[dp][e], ts[dp + 1][e], hh, ll);
        int base = (h * DINL + e0 + e) * DINL + d0 + dp;
        *(unsigned*)(g_w1th + base) = hh;
        *(unsigned*)(g_w1tl + base) = ll;
    }
}

// ---------------- LaCT forward: pure-copy fills + SwiGLU bwd epilogue ----------------
#define LPAD 40
__global__ __launch_bounds__(256) void lact_fwd_mma() {
    __shared__ __half Ah[128][LPAD], Al[128][LPAD];
    __shared__ __half B0h[64][LPAD], B0l[64][LPAD], B1h[64][LPAD], B1l[64][LPAD],
                      B2h[64][LPAD], B2l[64][LPAD];
    int bh = blockIdx.z, n = bh >> 2, h = bh & 3;
    int e0 = blockIdx.x * 64, c0 = blockIdx.y * 128;
    int tid = threadIdx.x, wid = tid >> 5, lane = tid & 31;
    int g = lane >> 2, c = lane & 3;
    int wm = (wid & 3) * 32, wn = (wid >> 2) * 32;
    float ag[2][4][4] = {}, ax[2][4][4] = {}, aw[2][4][4] = {};

    int r64 = tid >> 2, sg64 = (tid & 3) * 8;
    for (int k0 = 0; k0 < DINL; k0 += 32) {
        __syncthreads();
        #pragma unroll
        for (int p = 0; p < 2; p++) {
            int idx = tid + p * 256;
            int r = idx >> 2, sg = (idx & 3) * 8;
            int base = (n * CHK + c0 + r) * HSZ + h * DINL + k0 + sg;
            *(uint4*)&Ah[r][sg] = *(const uint4*)(g_xh + base);
            *(uint4*)&Al[r][sg] = *(const uint4*)(g_xl + base);
        }
        {
            int base = (h * DINL + e0 + r64) * DINL + k0 + sg64;
            *(uint4*)&B0h[r64][sg64] = *(const uint4*)(g_w0h + base);
            *(uint4*)&B0l[r64][sg64] = *(const uint4*)(g_w0l + base);
            *(uint4*)&B1h[r64][sg64] = *(const uint4*)(g_w2h + base);
            *(uint4*)&B1l[r64][sg64] = *(const uint4*)(g_w2l + base);
            *(uint4*)&B2h[r64][sg64] = *(const uint4*)(g_w1th + base);
            *(uint4*)&B2l[r64][sg64] = *(const uint4*)(g_w1tl + base);
        }
        __syncthreads();
        #pragma unroll
        for (int ks = 0; ks < 32; ks += 16) {
            unsigned ah[2][4], al[2][4];
            #pragma unroll
            for (int im = 0; im < 2; im++) {
                int mr = wm + im * 16;
                ah[im][0] = *(unsigned*)&Ah[mr + g][ks + 2 * c];
                ah[im][1] = *(unsigned*)&Ah[mr + g + 8][ks + 2 * c];
                ah[im][2] = *(unsigned*)&Ah[mr + g][ks + 2 * c + 8];
                ah[im][3] = *(unsigned*)&Ah[mr + g + 8][ks + 2 * c + 8];
                al[im][0] = *(unsigned*)&Al[mr + g][ks + 2 * c];
                al[im][1] = *(unsigned*)&Al[mr + g + 8][ks + 2 * c];
                al[im][2] = *(unsigned*)&Al[mr + g][ks + 2 * c + 8];
                al[im][3] = *(unsigned*)&Al[mr + g + 8][ks + 2 * c + 8];
            }
            #pragma unroll
            for (int jn = 0; jn < 4; jn++) {
                int nr = wn + jn * 8 + g;
                unsigned b0, b1, l0_, l1_;
                b0 = *(unsigned*)&B0h[nr][ks + 2 * c]; b1 = *(unsigned*)&B0h[nr][ks + 2 * c + 8];
                l0_ = *(unsigned*)&B0l[nr][ks + 2 * c]; l1_ = *(unsigned*)&B0l[nr][ks + 2 * c + 8];
                #pragma unroll
                for (int im = 0; im < 2; im++) {
                    mma_f16(ag[im][jn], ah[im][0], ah[im][1], ah[im][2], ah[im][3], b0, b1);
                    mma_f16(ag[im][jn], ah[im][0], ah[im][1], ah[im][2], ah[im][3], l0_, l1_);
                    mma_f16(ag[im][jn], al[im][0], al[im][1], al[im][2], al[im][3], b0, b1);
                }
                b0 = *(unsigned*)&B1h[nr][ks + 2 * c]; b1 = *(unsigned*)&B1h[nr][ks + 2 * c + 8];
                l0_ = *(unsigned*)&B1l[nr][ks + 2 * c]; l1_ = *(unsigned*)&B1l[nr][ks + 2 * c + 8];
                #pragma unroll
                for (int im = 0; im < 2; im++) {
                    mma_f16(ax[im][jn], ah[im][0], ah[im][1], ah[im][2], ah[im][3], b0, b1);
                    mma_f16(ax[im][jn], ah[im][0], ah[im][1], ah[im][2], ah[im][3], l0_, l1_);
                    mma_f16(ax[im][jn], al[im][0], al[im][1], al[im][2], al[im][3], b0, b1);
                }
                b0 = *(unsigned*)&B2h[nr][ks + 2 * c]; b1 = *(unsigned*)&B2h[nr][ks + 2 * c + 8];
                l0_ = *(unsigned*)&B2l[nr][ks + 2 * c]; l1_ = *(unsigned*)&B2l[nr][ks + 2 * c + 8];
                #pragma unroll
                for (int im = 0; im < 2; im++) {
                    mma_f16(aw[im][jn], ah[im][0], ah[im][1], ah[im][2], ah[im][3], b0, b1);
                    mma_f16(aw[im][jn], ah[im][0], ah[im][1], ah[im][2], ah[im][3], l0_, l1_);
                    mma_f16(aw[im][jn], al[im][0], al[im][1], al[im][2], al[im][3], b0, b1);
                }
            }
        }
    }
    float* hid = g_hidden + bh * CDSZ;
    float* dpr = g_dpre   + bh * CDSZ;
    float* dgp = g_dg     + bh * CDSZ;
    #pragma unroll
    for (int im = 0; im < 2; im++)
        #pragma unroll
        for (int jn = 0; jn < 4; jn++) {
            #pragma unroll
            for (int q = 0; q < 4; q++) {
                int row = c0 + wm + im * 16 + g + ((q >> 1) ? 8 : 0);
                int col = e0 + wn + jn * 8 + 2 * c + (q & 1);
                float gate = ag[im][jn][q], gg = ax[im][jn][q];
                float sg = 1.f / (1.f + __expf(-gate));
                float hs = gate * sg;
                float dhid = -aw[im][jn][q];
                int idx = row * DINL + col;
                hid[idx] = hs * gg;
                dgp[idx] = dhid * hs;
                dpr[idx] = dhid * gg * (sg + gate * sg * (1.f - sg));
            }
        }
}

// ---------------- LaCT weight grads + SGD -> fp16 split outputs ----------------
__global__ __launch_bounds__(256) void lact_dw_mma(const float* __restrict__ w0,
                                                   const float* __restrict__ w1,
                                                   const float* __restrict__ w2) {
    __shared__ __half Ah[128][LPAD], Al[128][LPAD], Bh[64][LPAD], Bl[64][LPAD];
    int z = blockIdx.z;
    int mode = z % 3, bh = z / 3;
    int i0 = blockIdx.y * 128, j0 = blockIdx.x * 64;
    int h = bh & 3;
    const float *P, *wb;
    __half *woh, *wol;
    float sign;
    if (mode == 0)      { P = g_dpre + bh * CDSZ; wb = w0 + h * WSZ;
                          woh = g_w0nh + bh * WSZ; wol = g_w0nl + bh * WSZ; sign = -1.f; }
    else if (mode == 1) { P = g_dg + bh * CDSZ; wb = w2 + h * WSZ;
                          woh = g_w2nh + bh * WSZ; wol = g_w2nl + bh * WSZ; sign = -1.f; }
    else                { P = g_hidden + bh * CDSZ; wb = w1 + h * WSZ;
                          woh = g_w1nh + bh * WSZ; wol = g_w1nl + bh * WSZ; sign = 1.f; }
    int tid = threadIdx.x, wid = tid >> 5, lane = tid & 31;
    int g = lane >> 2, c = lane & 3;
    int wm = (wid & 3) * 32, wn = (wid >> 2) * 32;
    float acc[2][4][4] = {};

    for (int k0 = 0; k0 < CHK; k0 += 32) {
        __syncthreads();
        if (mode != 2) {
            // A^T: transpose+cvt from fp32 dpre/dg [c][din]
            #pragma unroll
            for (int p = 0; p < 16; p++) {
                int idx = tid + p * 256;
                int kk = idx >> 7, ii = idx & 127;
                float v = P[(k0 + kk) * DINL + i0 + ii];
                __half hv, lv; split_h(v, hv, lv);
                Ah[ii][kk] = hv; Al[ii][kk] = lv;
            }
            // B: copy from X^T splits
            {
                int r = tid >> 2, sg = (tid & 3) * 8;
                int base = (bh * DINL + j0 + r) * CHK + k0 + sg;
                *(uint4*)&Bh[r][sg] = *(const uint4*)(g_xth + base);
                *(uint4*)&Bl[r][sg] = *(const uint4*)(g_xtl + base);
            }
        } else {
            // A: copy from X^T splits
            #pragma unroll
            for (int p = 0; p < 2; p++) {
                int idx = tid + p * 256;
                int r = idx >> 2, sg = (idx & 3) * 8;
                int base = (bh * DINL + i0 + r) * CHK + k0 + sg;
                *(uint4*)&Ah[r][sg] = *(const uint4*)(g_xth + base);
                *(uint4*)&Al[r][sg] = *(const uint4*)(g_xtl + base);
            }
            // B^T: transpose+cvt from fp32 hidden
            #pragma unroll
            for (int p = 0; p < 8; p++) {
                int idx = tid + p * 256;
                int kk = idx >> 6, jj = idx & 63;
                float v = P[(k0 + kk) * DINL + j0 + jj];
                __half hv, lv; split_h(v, hv, lv);
                Bh[jj][kk] = hv; Bl[jj][kk] = lv;
            }
        }
        __syncthreads();
        #pragma unroll
        for (int ks = 0; ks < 32; ks += 16) {
            unsigned ah[2][4], al[2][4];
            #pragma unroll
            for (int im = 0; im < 2; im++) {
                int mr = wm + im * 16;
                ah[im][0] = *(unsigned*)&Ah[mr + g][ks + 2 * c];
                ah[im][1] = *(unsigned*)&Ah[mr + g + 8][ks + 2 * c];
                ah[im][2] = *(unsigned*)&Ah[mr + g][ks + 2 * c + 8];
                ah[im][3] = *(unsigned*)&Ah[mr + g + 8][ks + 2 * c + 8];
                al[im][0] = *(unsigned*)&Al[mr + g][ks + 2 * c];
                al[im][1] = *(unsigned*)&Al[mr + g + 8][ks + 2 * c];
                al[im][2] = *(unsigned*)&Al[mr + g][ks + 2 * c + 8];
                al[im][3] = *(unsigned*)&Al[mr + g + 8][ks + 2 * c + 8];
            }
            #pragma unroll
            for (int jn = 0; jn < 4; jn++) {
                int nr = wn + jn * 8 + g;
                unsigned b0 = *(unsigned*)&Bh[nr][ks + 2 * c];
                unsigned b1 = *(unsigned*)&Bh[nr][ks + 2 * c + 8];
                unsigned l0_ = *(unsigned*)&Bl[nr][ks + 2 * c];
                unsigned l1_ = *(unsigned*)&Bl[nr][ks + 2 * c + 8];
                #pragma unroll
                for (int im = 0; im < 2; im++) {
                    mma_f16(acc[im][jn], ah[im][0], ah[im][1], ah[im][2], ah[im][3], b0, b1);
                    mma_f16(acc[im][jn], ah[im][0], ah[im][1], ah[im][2], ah[im][3], l0_, l1_);
                    mma_f16(acc[im][jn], al[im][0], al[im][1], al[im][2], al[im][3], b0, b1);
                }
            }
        }
    }
    #pragma unroll
    for (int im = 0; im < 2; im++)
        #pragma unroll
        for (int jn = 0; jn < 4; jn++) {
            int row = i0 + wm + im * 16 + g;
            int col = j0 + wn + jn * 8 + 2 * c;
            unsigned hh, ll;
            float v0 = wb[row * DINL + col]     + sign * acc[im][jn][0];
            float v1 = wb[row * DINL + col + 1] + sign * acc[im][jn][1];
            split_pack_h(v0, v1, hh, ll);
            *(unsigned*)(woh + row * DINL + col) = hh;
            *(unsigned*)(wol + row * DINL + col) = ll;
            v0 = wb[(row + 8) * DINL + col]     + sign * acc[im][jn][2];
            v1 = wb[(row + 8) * DINL + col + 1] + sign * acc[im][jn][3];
            split_pack_h(v0, v1, hh, ll);
            *(unsigned*)(woh + (row + 8) * DINL + col) = hh;
            *(unsigned*)(wol + (row + 8) * DINL + col) = ll;
        }
}

// ---------------- LaCT apply1: copy fills, u -> fp16 splits (scaled 2^-12) ----------------
__global__ __launch_bounds__(256) void lact_apply1_mma() {
    __shared__ __half Ah[128][LPAD], Al[128][LPAD];
    __shared__ __half B0h[64][LPAD], B0l[64][LPAD], B1h[64][LPAD], B1l[64][LPAD];
    int bh = blockIdx.z, n = bh >> 2, h = bh & 3;
    int e0 = blockIdx.x * 64, c0 = blockIdx.y * 128;
    int tid = threadIdx.x, wid = tid >> 5, lane = tid & 31;
    int g = lane >> 2, c = lane & 3;
    int wm = (wid & 3) * 32, wn = (wid >> 2) * 32;
    float a0[2][4][4] = {}, a2[2][4][4] = {};

    int r64 = tid >> 2, sg64 = (tid & 3) * 8;
    for (int k0 = 0; k0 < DINL; k0 += 32) {
        __syncthreads();
        #pragma unroll
        for (int p = 0; p < 2; p++) {
            int idx = tid + p * 256;
            int r = idx >> 2, sg = (idx & 3) * 8;
            int base = (n * CHK + c0 + r) * HSZ + h * DINL + k0 + sg;
            *(uint4*)&Ah[r][sg] = *(const uint4*)(g_xh + base);
            *(uint4*)&Al[r][sg] = *(const uint4*)(g_xl + base);
        }
        {
            int base = bh * WSZ + (e0 + r64) * DINL + k0 + sg64;
            *(uint4*)&B0h[r64][sg64] = *(const uint4*)(g_w0nh + base);
            *(uint4*)&B0l[r64][sg64] = *(const uint4*)(g_w0nl + base);
            *(uint4*)&B1h[r64][sg64] = *(const uint4*)(g_w2nh + base);
            *(uint4*)&B1l[r64][sg64] = *(const uint4*)(g_w2nl + base);
        }
        __syncthreads();
        #pragma unroll
        for (int ks = 0; ks < 32; ks += 16) {
            unsigned ah[2][4], al[2][4];
            #pragma unroll
            for (int im = 0; im < 2; im++) {
                int mr = wm + im * 16;
                ah[im][0] = *(unsigned*)&Ah[mr + g][ks + 2 * c];
                ah[im][1] = *(unsigned*)&Ah[mr + g + 8][ks + 2 * c];
                ah[im][2] = *(unsigned*)&Ah[mr + g][ks + 2 * c + 8];
                ah[im][3] = *(unsigned*)&Ah[mr + g + 8][ks + 2 * c + 8];
                al[im][0] = *(unsigned*)&Al[mr + g][ks + 2 * c];
                al[im][1] = *(unsigned*)&Al[mr + g + 8][ks + 2 * c];
                al[im][2] = *(unsigned*)&Al[mr + g][ks + 2 * c + 8];
                al[im][3] = *(unsigned*)&Al[mr + g + 8][ks + 2 * c + 8];
            }
            #pragma unroll
            for (int jn = 0; jn < 4; jn++) {
                int nr = wn + jn * 8 + g;
                unsigned b0, b1, l0_, l1_;
                b0 = *(unsigned*)&B0h[nr][ks + 2 * c]; b1 = *(unsigned*)&B0h[nr][ks + 2 * c + 8];
                l0_ = *(unsigned*)&B0l[nr][ks + 2 * c]; l1_ = *(unsigned*)&B0l[nr][ks + 2 * c + 8];
                #pragma unroll
                for (int im = 0; im < 2; im++) {
                    mma_f16(a0[im][jn], ah[im][0], ah[im][1], ah[im][2], ah[im][3], b0, b1);
                    mma_f16(a0[im][jn], ah[im][0], ah[im][1], ah[im][2], ah[im][3], l0_, l1_);
                    mma_f16(a0[im][jn], al[im][0], al[im][1], al[im][2], al[im][3], b0, b1);
                }
                b0 = *(unsigned*)&B1h[nr][ks + 2 * c]; b1 = *(unsigned*)&B1h[nr][ks + 2 * c + 8];
                l0_ = *(unsigned*)&B1l[nr][ks + 2 * c]; l1_ = *(unsigned*)&B1l[nr][ks + 2 * c + 8];
                #pragma unroll
                for (int im = 0; im < 2; im++) {
                    mma_f16(a2[im][jn], ah[im][0], ah[im][1], ah[im][2], ah[im][3], b0, b1);
                    mma_f16(a2[im][jn], ah[im][0], ah[im][1], ah[im][2], ah[im][3], l0_, l1_);
                    mma_f16(a2[im][jn], al[im][0], al[im][1], al[im][2], al[im][3], b0, b1);
                }
            }
        }
    }
    #pragma unroll
    for (int im = 0; im < 2; im++)
        #pragma unroll
        for (int jn = 0; jn < 4; jn++) {
            int row = c0 + wm + im * 16 + g;
            int col = e0 + wn + jn * 8 + 2 * c;
            float gq0 = a0[im][jn][0], gq1 = a0[im][jn][1];
            float u0 = gq0 / (1.f + __expf(-gq0)) * a2[im][jn][0] * USCALE;
            float u1 = gq1 / (1.f + __expf(-gq1)) * a2[im][jn][1] * USCALE;
            unsigned hh, ll;
            split_pack_h(u0, u1, hh, ll);
            *(unsigned*)(g_uh + bh * CDSZ + row * DINL + col) = hh;
            *(unsigned*)(g_ul + bh * CDSZ + row * DINL + col) = ll;
            gq0 = a0[im][jn][2]; gq1 = a0[im][jn][3];
            u0 = gq0 / (1.f + __expf(-gq0)) * a2[im][jn][2] * USCALE;
            u1 = gq1 / (1.f + __expf(-gq1)) * a2[im][jn][3] * USCALE;
            split_pack_h(u0, u1, hh, ll);
            *(unsigned*)(g_uh + bh * CDSZ + (row + 8) * DINL + col) = hh;
            *(unsigned*)(g_ul + bh * CDSZ + (row + 8) * DINL + col) = ll;
        }
}

// ---------------- LaCT apply2: copy fills, out += (u @ w1n^T) * 2^12 ----------------
__global__ __launch_bounds__(256) void lact_apply2_mma(float* __restrict__ out) {
    __shared__ __half Ah[128][LPAD], Al[128][LPAD], Bh[64][LPAD], Bl[64][LPAD];
    int bh = blockIdx.z, n = bh >> 2, h = bh & 3;
    int d0 = blockIdx.x * 64, c0 = blockIdx.y * 128;
    int tid = threadIdx.x, wid = tid >> 5, lane = tid & 31;
    int g = lane >> 2, c = lane & 3;
    int wm = (wid & 3) * 32, wn = (wid >> 2) * 32;
    float acc[2][4][4] = {};

    int r64 = tid >> 2, sg64 = (tid & 3) * 8;
    for (int k0 = 0; k0 < DINL; k0 += 32) {
        __syncthreads();
        #pragma unroll
        for (int p = 0; p < 2; p++) {
            int idx = tid + p * 256;
            int r = idx >> 2, sg = (idx & 3) * 8;
            int base = bh * CDSZ + (c0 + r) * DINL + k0 + sg;
            *(uint4*)&Ah[r][sg] = *(const uint4*)(g_uh + base);
            *(uint4*)&Al[r][sg] = *(const uint4*)(g_ul + base);
        }
        {
            int base = bh * WSZ + (d0 + r64) * DINL + k0 + sg64;
            *(uint4*)&Bh[r64][sg64] = *(const uint4*)(g_w1nh + base);
            *(uint4*)&Bl[r64][sg64] = *(const uint4*)(g_w1nl + base);
        }
        __syncthreads();
        #pragma unroll
        for (int ks = 0; ks < 32; ks += 16) {
            unsigned ah[2][4], al[2][4];
            #pragma unroll
            for (int im = 0; im < 2; im++) {
                int mr = wm + im * 16;
                ah[im][0] = *(unsigned*)&Ah[mr + g][ks + 2 * c];
                ah[im][1] = *(unsigned*)&Ah[mr + g + 8][ks + 2 * c];
                ah[im][2] = *(unsigned*)&Ah[mr + g][ks + 2 * c + 8];
                ah[im][3] = *(unsigned*)&Ah[mr + g + 8][ks + 2 * c + 8];
                al[im][0] = *(unsigned*)&Al[mr + g][ks + 2 * c];
                al[im][1] = *(unsigned*)&Al[mr + g + 8][ks + 2 * c];
                al[im][2] = *(unsigned*)&Al[mr + g][ks + 2 * c + 8];
                al[im][3] = *(unsigned*)&Al[mr + g + 8][ks + 2 * c + 8];
            }
            #pragma unroll
            for (int jn = 0; jn < 4; jn++) {
                int nr = wn + jn * 8 + g;
                unsigned b0 = *(unsigned*)&Bh[nr][ks + 2 * c];
                unsigned b1 = *(unsigned*)&Bh[nr][ks + 2 * c + 8];
                unsigned l0_ = *(unsigned*)&Bl[nr][ks + 2 * c];
                unsigned l1_ = *(unsigned*)&Bl[nr][ks + 2 * c + 8];
                #pragma unroll
                for (int im = 0; im < 2; im++) {
                    mma_f16(acc[im][jn], ah[im][0], ah[im][1], ah[im][2], ah[im][3], b0, b1);
                    mma_f16(acc[im][jn], ah[im][0], ah[im][1], ah[im][2], ah[im][3], l0_, l1_);
                    mma_f16(acc[im][jn], al[im][0], al[im][1], al[im][2], al[im][3], b0, b1);
                }
            }
        }
    }
    #pragma unroll
    for (int im = 0; im < 2; im++)
        #pragma unroll
        for (int jn = 0; jn < 4; jn++) {
            #pragma unroll
            for (int q = 0; q < 4; q++) {
                int row = c0 + wm + im * 16 + g + ((q >> 1) ? 8 : 0);
                int col = d0 + wn + jn * 8 + 2 * c + (q & 1);
                out[(n * CHK + row) * HSZ + h * DINL + col] += acc[im][jn][q] * USCALE_INV;
            }
        }
}

// ---------------- launch ----------------
extern "C" void kernel_launch(void* const* d_in, const int* in_sizes, int n_in,
                              void* d_out, int out_size) {
    const float* x   = (const float*)d_in[0];
    const float* lnw = (const float*)d_in[1];
    const float* lnb = (const float*)d_in[2];
    const float* ipw = (const float*)d_in[3];
    const float* ipb = (const float*)d_in[4];
    const float* opw = (const float*)d_in[5];
    const float* opb = (const float*)d_in[6];
    const float* w0  = (const float*)d_in[7];
    const float* w1  = (const float*)d_in[8];
    const float* w2  = (const float*)d_in[9];
    float* out = (float*)d_out;

    ln_kernel<<<SQ, 256>>>(x, lnw, lnb);
    // lact precompute (depends only on xn / weights)
    cvt_x_kernel<<<SQ * HSZ / 1024, 256>>>();
    cvt_xt_kernel<<<dim3(CHK / 64, DINL / 64, NBH), 256>>>();
    cvt_w_kernel<<<NHL * WSZ / 1024, 256>>>(w0, w2);
    cvt_w1t_kernel<<<dim3(DINL / 64, DINL / 64, NHL), 256>>>(w1);
    // attention path
    gemm_mma_kernel<<<dim3(3 * HSZ / 64, SQ / 128), 256>>>(ipw, ipb, nullptr, 0, 3 * HSZ, HSZ);
    cvt_k_kernel<<<dim3(SQ / 64, NHA), 256>>>();
    cvt_v_kernel<<<dim3(SQ / 64, NHA), 256>>>();
    attn2_kernel<<<dim3(SQ / 256, NHA), 256>>>();
    gemm_mma_kernel<<<dim3(HSZ / 64, SQ / 128), 256>>>(opw, opb, out, 1, HSZ, HSZ);
    // lact
    lact_fwd_mma<<<dim3(DINL / 64, CHK / 128, NBH), 256>>>();
    lact_dw_mma<<<dim3(DINL / 64, DINL / 128, NBH * 3), 256>>>(w0, w1, w2);
    lact_apply1_mma<<<dim3(DINL / 64, CHK / 128, NBH), 256>>>();
    lact_apply2_mma<<<dim3(DINL / 64, CHK / 128, NBH), 256>>>(out);
}